// round 6
// baseline (speedup 1.0000x reference)
#include <cuda_runtime.h>
#include <cuda_bf16.h>
#include <math.h>
#include <cstdint>

#define BSZ 16
#define SEQ 512
#define DM  512
#define NH  8
#define DKH 64
#define MTOT (BSZ*SEQ)            // 8192
#define NEG_INF (__int_as_float(0xff800000))
#define QKVPLN (128*512*64)       // elements per plane
#define APLN (128u*512u*512u)

// ===================== scratch =====================
__device__ __nv_bfloat16 g_Qb [2*QKVPLN];
__device__ __nv_bfloat16 g_Kb [2*QKVPLN];
__device__ __nv_bfloat16 g_Vtb[2*QKVPLN];
__device__ float         g_S  [APLN];
__device__ __nv_bfloat16 g_A  [2*APLN];
__device__ float g_X [MTOT*DM];
__device__ float g_Y [MTOT*DM];
__device__ float g_H [MTOT*128];
__device__ unsigned long long g_sacc[4];
__device__ float2 g_rowst[MTOT];
__device__ unsigned char g_Wpk[5u*1024u*1024u];

// ===================== asm helpers =====================
__device__ __forceinline__ uint32_t smem_to_u32(const void* p) {
    uint32_t a;
    asm("{ .reg .u64 t; cvta.to.shared.u64 t, %1; cvt.u32.u64 %0, t; }" : "=r"(a) : "l"(p));
    return a;
}
__device__ __forceinline__ void ldsm4(uint32_t* r, uint32_t addr) {
    asm volatile("ldmatrix.sync.aligned.m8n8.x4.shared.b16 {%0,%1,%2,%3}, [%4];"
        : "=r"(r[0]), "=r"(r[1]), "=r"(r[2]), "=r"(r[3]) : "r"(addr));
}
__device__ __forceinline__ void mma16816(float* c, const uint32_t* a, const uint32_t* b) {
    asm volatile("mma.sync.aligned.m16n8k16.row.col.f32.bf16.bf16.f32 "
        "{%0,%1,%2,%3}, {%4,%5,%6,%7}, {%8,%9}, {%0,%1,%2,%3};"
        : "+f"(c[0]), "+f"(c[1]), "+f"(c[2]), "+f"(c[3])
        : "r"(a[0]), "r"(a[1]), "r"(a[2]), "r"(a[3]), "r"(b[0]), "r"(b[1]));
}
__device__ __forceinline__ uint32_t pack_hi(float x, float y, float& lx, float& ly) {
    __nv_bfloat162 h = __floats2bfloat162_rn(x, y);
    lx = x - __bfloat162float(h.x);
    ly = y - __bfloat162float(h.y);
    return *reinterpret_cast<uint32_t*>(&h);
}
__device__ __forceinline__ uint32_t pack_lo(float lx, float ly) {
    __nv_bfloat162 l = __floats2bfloat162_rn(lx, ly);
    return *reinterpret_cast<uint32_t*>(&l);
}
#define CP_ASYNC16(dst, src) \
    asm volatile("cp.async.cg.shared.global [%0], [%1], 16;" :: "r"(dst), "l"(src))
#define CP_COMMIT() asm volatile("cp.async.commit_group;" ::: "memory")
#define CP_WAIT0()  asm volatile("cp.async.wait_group 0;"  ::: "memory")

// ===================== fused weight pre-split =====================
__global__ __launch_bounds__(256) void wconv_all(
    const float* __restrict__ Wq, const float* __restrict__ Wk,
    const float* __restrict__ Wv, const float* __restrict__ Wo,
    const float* __restrict__ Wi2, unsigned char* __restrict__ dst)
{
    if (blockIdx.x == 0 && threadIdx.x < 4) g_sacc[threadIdx.x] = 0ull;
    int bb = blockIdx.x;
    const float* W; unsigned char* d; int K;
    if      (bb < 512)  { W = Wq;  d = dst;              K = 512; }
    else if (bb < 1024) { W = Wk;  d = dst + 1048576u;   K = 512; bb -= 512; }
    else if (bb < 1536) { W = Wv;  d = dst + 2097152u;   K = 512; bb -= 1024; }
    else if (bb < 2048) { W = Wo;  d = dst + 3145728u;   K = 512; bb -= 1536; }
    else                { W = Wi2; d = dst + 4194304u;   K = 128; bb -= 2048; }
    int NK = (K == 512) ? 262144 : 65536;
    int idx = bb * 256 + threadIdx.x;
    int halfK = K >> 1;
    int n = idx / halfK;
    int k = (idx - n * halfK) * 2;
    float x0 = W[(size_t)n * K + k];
    float x1 = W[(size_t)n * K + k + 1];
    float lx, ly;
    uint32_t hp = pack_hi(x0, x1, lx, ly);
    uint32_t lp = pack_lo(lx, ly);
    *(uint32_t*)(d + (size_t)(n * K + k) * 2)                  = hp;
    *(uint32_t*)(d + (size_t)NK * 2 + (size_t)(n * K + k) * 2) = lp;
}

// ===================== projection / misc GEMM (mma.sync, bf16 3-term) =============
// MODE 3: C = addsrc + scale[0]*(acc+bias).  MODE 4: Q planes (1/8).  MODE 5: K planes.
// MODE 6: V^T planes.  MODE 7: plain out, LayerNorm applied to A while staging.
#define TG2_BUF 20480
#define TG2_SMEM 81920

template<int MODE>
__global__ __launch_bounds__(256, 1) void tgemm_kernel(
    const float* __restrict__ A, const unsigned char* __restrict__ Bpk,
    const float* __restrict__ bias, float* __restrict__ C, __nv_bfloat16* __restrict__ Cb,
    int N, int K, int NK,
    const float* __restrict__ addsrc, const float* __restrict__ scale,
    const float* __restrict__ lng, const float* __restrict__ lnb)
{
    extern __shared__ char sm[];
    const uint32_t sbase = smem_to_u32(sm);
    const int tid = threadIdx.x;
    const int wid = tid >> 5, lane = tid & 31;
    const int bm = blockIdx.y * 128, bn = blockIdx.x * 128;
    const int wm = (wid >> 2) * 64, wn = (wid & 3) * 32;
    const int S = K >> 5;

    const unsigned char* BhiP = Bpk;
    const unsigned char* BloP = Bpk + (size_t)NK * 2;

    const int a_row = tid >> 3, a_q = tid & 7;
    const int b_row = tid >> 2, b_q = tid & 3;

    float4 aL[4];
    float acc[16][4];
#pragma unroll
    for (int i = 0; i < 16; i++)
#pragma unroll
        for (int j = 0; j < 4; j++) acc[i][j] = 0.f;

    auto loadA = [&](int s) {
        int k0 = s * 32;
#pragma unroll
        for (int it = 0; it < 4; it++)
            aL[it] = *(const float4*)(A + (size_t)(bm + a_row + it*32) * K + k0 + a_q * 4);
    };
    auto issueB = [&](int s, int buf) {
        int k0 = s * 32;
        uint32_t dbase = sbase + 40960 + buf * TG2_BUF;
#pragma unroll
        for (int it = 0; it < 2; it++) {
            int row = b_row + it * 64;
            size_t off = ((size_t)(bn + row) * K + k0 + b_q * 8) * 2;
            uint32_t d = dbase + row * 80 + b_q * 16;
            CP_ASYNC16(d,         BhiP + off);
            CP_ASYNC16(d + 10240, BloP + off);
        }
    };
    auto storeA = [&](int buf, int k0) {
        char* base = sm + buf * TG2_BUF;
        float4 g4, b4;
        if (MODE == 7) {
            g4 = *(const float4*)(lng + k0 + a_q * 4);
            b4 = *(const float4*)(lnb + k0 + a_q * 4);
        }
#pragma unroll
        for (int it = 0; it < 4; it++) {
            int row = a_row + it * 32;
            float x0 = aL[it].x, x1 = aL[it].y, x2 = aL[it].z, x3 = aL[it].w;
            if (MODE == 7) {
                float2 st = g_rowst[bm + row];
                x0 = (x0 - st.x) * st.y * g4.x + b4.x;
                x1 = (x1 - st.x) * st.y * g4.y + b4.y;
                x2 = (x2 - st.x) * st.y * g4.z + b4.z;
                x3 = (x3 - st.x) * st.y * g4.w + b4.w;
            }
            float l0, l1, l2, l3;
            uint2 hp; hp.x = pack_hi(x0, x1, l0, l1);
                      hp.y = pack_hi(x2, x3, l2, l3);
            uint2 lp; lp.x = pack_lo(l0, l1); lp.y = pack_lo(l2, l3);
            *(uint2*)(base + row * 80 + a_q * 8)         = hp;
            *(uint2*)(base + 10240 + row * 80 + a_q * 8) = lp;
        }
    };

    const int aoff   = (lane & 15) * 80 + (lane >> 4) * 16;
    const int boff_n = ((lane >> 4) << 3) + (lane & 7);
    const int bsel   = ((lane >> 3) & 1) * 16;

    auto compute = [&](int buf) {
        uint32_t Abase = sbase + buf * TG2_BUF;
        uint32_t Bbase = sbase + 40960 + buf * TG2_BUF;
#pragma unroll
        for (int kh = 0; kh < 2; kh++) {
            uint32_t bh[8], bl[8], a[16];
#pragma unroll
            for (int nf2 = 0; nf2 < 2; nf2++) {
                uint32_t baddr = Bbase + (wn + nf2 * 16 + boff_n) * 80 + kh * 32 + bsel;
                ldsm4(bh + nf2 * 4, baddr);
                ldsm4(bl + nf2 * 4, baddr + 10240);
            }
#pragma unroll
            for (int mf = 0; mf < 4; mf++)
                ldsm4(a + mf * 4, Abase + (wm + mf * 16) * 80 + kh * 32 + aoff);
#pragma unroll
            for (int mf = 0; mf < 4; mf++)
#pragma unroll
                for (int nf = 0; nf < 4; nf++)
                    mma16816(acc[mf * 4 + nf], a + mf * 4, bh + nf * 2);
#pragma unroll
            for (int mf = 0; mf < 4; mf++)
#pragma unroll
                for (int nf = 0; nf < 4; nf++)
                    mma16816(acc[mf * 4 + nf], a + mf * 4, bl + nf * 2);
#pragma unroll
            for (int mf = 0; mf < 4; mf++)
                ldsm4(a + mf * 4, Abase + 10240 + (wm + mf * 16) * 80 + kh * 32 + aoff);
#pragma unroll
            for (int mf = 0; mf < 4; mf++)
#pragma unroll
                for (int nf = 0; nf < 4; nf++)
                    mma16816(acc[mf * 4 + nf], a + mf * 4, bh + nf * 2);
        }
    };

    loadA(0); issueB(0, 0); CP_COMMIT();
    storeA(0, 0);
    for (int s = 0; s < S; s++) {
        CP_WAIT0();
        __syncthreads();
        if (s + 1 < S) { issueB(s + 1, (s + 1) & 1); CP_COMMIT(); loadA(s + 1); }
        compute(s & 1);
        if (s + 1 < S) storeA((s + 1) & 1, (s + 1) * 32);
    }

    const float isc = (MODE == 3) ? scale[0] : 0.f;
#pragma unroll
    for (int mf = 0; mf < 4; mf++) {
#pragma unroll
        for (int nf = 0; nf < 4; nf++) {
            float* cc = acc[mf * 4 + nf];
            int col = bn + wn + nf * 8 + (lane & 3) * 2;
            float b0 = bias[col], b1 = bias[col + 1];
#pragma unroll
            for (int rp = 0; rp < 2; rp++) {
                int m = bm + wm + mf * 16 + (lane >> 2) + rp * 8;
                float v0 = cc[rp * 2 + 0] + b0;
                float v1 = cc[rp * 2 + 1] + b1;
                if (MODE == 7) {
                    *(float2*)(C + (size_t)m * N + col) = make_float2(v0, v1);
                } else if (MODE == 3) {
                    const float* ad = addsrc + (size_t)m * N + col;
                    *(float2*)(C + (size_t)m * N + col) =
                        make_float2(ad[0] + isc * v0, ad[1] + isc * v1);
                } else if (MODE == 4 || MODE == 5) {
                    if (MODE == 4) { v0 *= 0.125f; v1 *= 0.125f; }
                    int bb = m >> 9, si = m & 511, hh = col >> 6, d = col & 63;
                    size_t idx = (((size_t)(bb * NH + hh)) * SEQ + si) * DKH + d;
                    float l0, l1;
                    uint32_t hp = pack_hi(v0, v1, l0, l1);
                    uint32_t lp = pack_lo(l0, l1);
                    *(uint32_t*)&Cb[idx]          = hp;
                    *(uint32_t*)&Cb[idx + QKVPLN] = lp;
                } else {  // MODE 6
                    int bb = m >> 9, si = m & 511, hh = col >> 6, d = col & 63;
                    size_t i0 = (((size_t)(bb * NH + hh)) * DKH + d) * SEQ + si;
                    __nv_bfloat16 h0 = __float2bfloat16(v0);
                    __nv_bfloat16 h1 = __float2bfloat16(v1);
                    Cb[i0]                = h0;
                    Cb[i0 + QKVPLN]       = __float2bfloat16(v0 - __bfloat162float(h0));
                    Cb[i0 + SEQ]          = h1;
                    Cb[i0 + SEQ + QKVPLN] = __float2bfloat16(v1 - __bfloat162float(h1));
                }
            }
        }
    }
}

// ===================== QK^T batched GEMM (causal tile skip, cp.async) ==============
#define SK_SMEM 73728

__global__ __launch_bounds__(256, 1) void qk_kernel()
{
    if (blockIdx.x > blockIdx.y) return;
    extern __shared__ char sm[];
    const uint32_t sbase = smem_to_u32(sm);
    const int bn = blockIdx.x * 128, bm = blockIdx.y * 128;
    const int bh = blockIdx.z;
    const int tid = threadIdx.x, wid = tid >> 5, lane = tid & 31;

#pragma unroll
    for (int pl = 0; pl < 2; pl++) {
        const unsigned char* qsrc = (const unsigned char*)(g_Qb + (size_t)pl * QKVPLN + ((size_t)bh * 512 + bm) * 64);
        const unsigned char* ksrc = (const unsigned char*)(g_Kb + (size_t)pl * QKVPLN + ((size_t)bh * 512 + bn) * 64);
        uint32_t qdst = sbase + pl * 18432;
        uint32_t kdst = sbase + 36864 + pl * 18432;
#pragma unroll
        for (int it = 0; it < 4; it++) {
            int idx = it * 256 + tid;
            int r = idx >> 3, c = idx & 7;
            CP_ASYNC16(qdst + r * 144 + c * 16, qsrc + (size_t)r * 128 + c * 16);
            CP_ASYNC16(kdst + r * 144 + c * 16, ksrc + (size_t)r * 128 + c * 16);
        }
    }
    CP_COMMIT(); CP_WAIT0();
    __syncthreads();

    const int wm = (wid >> 2) * 64, wn = (wid & 3) * 32;
    const int aoff   = (lane & 15) * 144 + (lane >> 4) * 16;
    const int boff_n = ((lane >> 4) << 3) + (lane & 7);
    const int bsel   = ((lane >> 3) & 1) * 16;
    const uint32_t QHI = sbase, QLO = sbase + 18432;
    const uint32_t KHI = sbase + 36864;

    float acc[16][4];
#pragma unroll
    for (int i = 0; i < 16; i++)
#pragma unroll
        for (int j = 0; j < 4; j++) acc[i][j] = 0.f;

#pragma unroll
    for (int kh = 0; kh < 4; kh++) {
        uint32_t bh_[8], bl_[8], a[16];
#pragma unroll
        for (int nf2 = 0; nf2 < 2; nf2++) {
            uint32_t baddr = KHI + (wn + nf2 * 16 + boff_n) * 144 + kh * 32 + bsel;
            ldsm4(bh_ + nf2 * 4, baddr);
            ldsm4(bl_ + nf2 * 4, baddr + 18432);
        }
#pragma unroll
        for (int mf = 0; mf < 4; mf++)
            ldsm4(a + mf * 4, QHI + (wm + mf * 16) * 144 + kh * 32 + aoff);
#pragma unroll
        for (int mf = 0; mf < 4; mf++)
#pragma unroll
            for (int nf = 0; nf < 4; nf++)
                mma16816(acc[mf * 4 + nf], a + mf * 4, bh_ + nf * 2);
#pragma unroll
        for (int mf = 0; mf < 4; mf++)
#pragma unroll
            for (int nf = 0; nf < 4; nf++)
                mma16816(acc[mf * 4 + nf], a + mf * 4, bl_ + nf * 2);
#pragma unroll
        for (int mf = 0; mf < 4; mf++)
            ldsm4(a + mf * 4, QLO + (wm + mf * 16) * 144 + kh * 32 + aoff);
#pragma unroll
        for (int mf = 0; mf < 4; mf++)
#pragma unroll
            for (int nf = 0; nf < 4; nf++)
                mma16816(acc[mf * 4 + nf], a + mf * 4, bh_ + nf * 2);
    }

    float* Sp = g_S + (size_t)bh * 512 * 512;
#pragma unroll
    for (int mf = 0; mf < 4; mf++)
#pragma unroll
        for (int nf = 0; nf < 4; nf++) {
            float* cc = acc[mf * 4 + nf];
            int col = bn + wn + nf * 8 + (lane & 3) * 2;
#pragma unroll
            for (int rp = 0; rp < 2; rp++) {
                int m = bm + wm + mf * 16 + (lane >> 2) + rp * 8;
                *(float2*)(Sp + (size_t)m * 512 + col) =
                    make_float2(cc[rp * 2], cc[rp * 2 + 1]);
            }
        }
}

// ===================== row kernel (causal-truncated tiles) =========================
__global__ __launch_bounds__(256) void row_kernel(const float* __restrict__ gammas)
{
    const int bh = blockIdx.y, h = bh & 7;
    const int wid = threadIdx.x >> 5, lane = threadIdx.x & 31;
    const int i = blockIdx.x * 8 + wid;
    const int Ti = i >> 7;                       // last tile index needed
    __nv_bfloat16* Ahi = g_A + ((size_t)bh * 512 + i) * 512;

    if (i == 0) {
        uint2 z = make_uint2(0u, 0u);
        int j0 = 4 * lane;
        *(uint2*)(Ahi + j0)        = z;
        *(uint2*)(Ahi + APLN + j0) = z;
        return;
    }

    float gv = gammas[h];
    float gam = -(fmaxf(gv, 0.f) + log1pf(__expf(-fabsf(gv))));

    const float4* Srow = (const float4*)(g_S + ((size_t)bh * 512 + i) * 512);
    float sc[4][4], e[4][4], ls[4];
#pragma unroll
    for (int t = 0; t < 4; t++) {
        if (t > Ti) { ls[t] = 0.f; continue; }
        float4 sv = Srow[lane + 32 * t];
        int j0 = 4 * (lane + 32 * t);
        sc[t][0] = (j0 + 0 < i) ? sv.x : NEG_INF;
        sc[t][1] = (j0 + 1 < i) ? sv.y : NEG_INF;
        sc[t][2] = (j0 + 2 < i) ? sv.z : NEG_INF;
        sc[t][3] = (j0 + 3 < i) ? sv.w : NEG_INF;
    }

    float m = NEG_INF;
#pragma unroll
    for (int t = 0; t < 4; t++) {
        if (t > Ti) break;
#pragma unroll
        for (int l = 0; l < 4; l++) m = fmaxf(m, sc[t][l]);
    }
#pragma unroll
    for (int off = 16; off; off >>= 1)
        m = fmaxf(m, __shfl_xor_sync(0xffffffffu, m, off));

#pragma unroll
    for (int t = 0; t < 4; t++) {
        if (t > Ti) break;
        ls[t] = 0.f;
#pragma unroll
        for (int l = 0; l < 4; l++) { e[t][l] = __expf(sc[t][l] - m); ls[t] += e[t][l]; }
    }
    float excl[4], tot[4];
#pragma unroll
    for (int t = 0; t < 4; t++) {
        if (t > Ti) break;
        float x = ls[t];
#pragma unroll
        for (int off = 1; off < 32; off <<= 1) {
            float y = __shfl_up_sync(0xffffffffu, x, off);
            if (lane >= off) x += y;
        }
        excl[t] = x - ls[t];
        tot[t]  = __shfl_sync(0xffffffffu, x, 31);
    }
    float baseA[4], T = 0.f;
#pragma unroll
    for (int t = 0; t < 4; t++) {
        if (t > Ti) break;
        baseA[t] = T; T += tot[t];
    }
    float invT = 1.f / T;

#pragma unroll
    for (int t = 0; t < 4; t++) {
        if (t > Ti) break;
        float run = baseA[t] + excl[t];
#pragma unroll
        for (int l = 0; l < 4; l++) {
            run += e[t][l];
            int j = 4 * lane + 128 * t + l;
            float suf  = fmaxf(T - run, 0.f);
            float dist = sqrtf(fmaxf(suf * invT * (float)(i - j), 0.f));
            float tmp  = __expf(dist * gam);
            tmp = fminf(fmaxf(tmp, 1e-5f), 1e5f);
            sc[t][l] = (j < i) ? sc[t][l] * tmp : NEG_INF;
        }
    }

    float m2 = NEG_INF;
#pragma unroll
    for (int t = 0; t < 4; t++) {
        if (t > Ti) break;
#pragma unroll
        for (int l = 0; l < 4; l++) m2 = fmaxf(m2, sc[t][l]);
    }
#pragma unroll
    for (int off = 16; off; off >>= 1)
        m2 = fmaxf(m2, __shfl_xor_sync(0xffffffffu, m2, off));
    float Z = 0.f;
#pragma unroll
    for (int t = 0; t < 4; t++) {
        if (t > Ti) break;
#pragma unroll
        for (int l = 0; l < 4; l++) { e[t][l] = __expf(sc[t][l] - m2); Z += e[t][l]; }
    }
#pragma unroll
    for (int off = 16; off; off >>= 1)
        Z += __shfl_xor_sync(0xffffffffu, Z, off);
    float invZ = 1.f / Z;

#pragma unroll
    for (int t = 0; t < 4; t++) {
        if (t > Ti) break;
        float a0 = e[t][0] * invZ, a1 = e[t][1] * invZ;
        float a2 = e[t][2] * invZ, a3 = e[t][3] * invZ;
        float l0, l1, l2, l3;
        uint2 hp; hp.x = pack_hi(a0, a1, l0, l1); hp.y = pack_hi(a2, a3, l2, l3);
        uint2 lp; lp.x = pack_lo(l0, l1);         lp.y = pack_lo(l2, l3);
        int j0 = 4 * (lane + 32 * t);
        *(uint2*)(Ahi + j0)        = hp;
        *(uint2*)(Ahi + APLN + j0) = lp;
    }
}

// ===================== AV batched GEMM (causal K-limit, cp.async) ==================
#define AV_BUF 30720
#define AV_SMEM 61440

__global__ __launch_bounds__(256, 1) void av_kernel()
{
    extern __shared__ char sm[];
    const uint32_t sbase = smem_to_u32(sm);
    const int bm = blockIdx.x * 128;
    const int bh = blockIdx.y;
    const int b = bh >> 3, h = bh & 7;
    const int tid = threadIdx.x, wid = tid >> 5, lane = tid & 31;
    const int nst = (bm + 128) >> 5;

    float acc[8][4];
#pragma unroll
    for (int i = 0; i < 8; i++)
#pragma unroll
        for (int j = 0; j < 4; j++) acc[i][j] = 0.f;

    auto issueAV = [&](int s, int buf) {
        uint32_t base = sbase + buf * AV_BUF;
#pragma unroll
        for (int it = 0; it < 4; it++) {
            int idx = it * 256 + tid;
            int pl = idx >> 9, r = (idx >> 2) & 127, c = idx & 3;
            const unsigned char* src = (const unsigned char*)(g_A + (size_t)pl * APLN +
                ((size_t)bh * 512 + bm + r) * 512 + s * 32 + c * 8);
            CP_ASYNC16(base + pl * 10240 + r * 80 + c * 16, src);
        }
#pragma unroll
        for (int it = 0; it < 2; it++) {
            int idx = it * 256 + tid;
            int pl = idx >> 8, d = (idx >> 2) & 63, c = idx & 3;
            const unsigned char* src = (const unsigned char*)(g_Vtb + (size_t)pl * QKVPLN +
                ((size_t)bh * 64 + d) * 512 + s * 32 + c * 8);
            CP_ASYNC16(base + 20480 + pl * 5120 + d * 80 + c * 16, src);
        }
    };

    const int wm = (wid >> 1) * 32, wn = (wid & 1) * 32;
    const int aoff   = (lane & 15) * 80 + (lane >> 4) * 16;
    const int boff_n = ((lane >> 4) << 3) + (lane & 7);
    const int bsel   = ((lane >> 3) & 1) * 16;

    auto compute = [&](int buf) {
        uint32_t Ab = sbase + buf * AV_BUF;
        uint32_t Vb = Ab + 20480;
#pragma unroll
        for (int kh = 0; kh < 2; kh++) {
            uint32_t bh_[8], bl_[8], a[8];
#pragma unroll
            for (int nf2 = 0; nf2 < 2; nf2++) {
                uint32_t baddr = Vb + (wn + nf2 * 16 + boff_n) * 80 + kh * 32 + bsel;
                ldsm4(bh_ + nf2 * 4, baddr);
                ldsm4(bl_ + nf2 * 4, baddr + 5120);
            }
#pragma unroll
            for (int mf = 0; mf < 2; mf++)
                ldsm4(a + mf * 4, Ab + (wm + mf * 16) * 80 + kh * 32 + aoff);
#pragma unroll
            for (int mf = 0; mf < 2; mf++)
#pragma unroll
                for (int nf = 0; nf < 4; nf++)
                    mma16816(acc[mf * 4 + nf], a + mf * 4, bh_ + nf * 2);
#pragma unroll
            for (int mf = 0; mf < 2; mf++)
#pragma unroll
                for (int nf = 0; nf < 4; nf++)
                    mma16816(acc[mf * 4 + nf], a + mf * 4, bl_ + nf * 2);
#pragma unroll
            for (int mf = 0; mf < 2; mf++)
                ldsm4(a + mf * 4, Ab + 10240 + (wm + mf * 16) * 80 + kh * 32 + aoff);
#pragma unroll
            for (int mf = 0; mf < 2; mf++)
#pragma unroll
                for (int nf = 0; nf < 4; nf++)
                    mma16816(acc[mf * 4 + nf], a + mf * 4, bh_ + nf * 2);
        }
    };

    issueAV(0, 0); CP_COMMIT();
    for (int s = 0; s < nst; s++) {
        CP_WAIT0();
        __syncthreads();
        if (s + 1 < nst) { issueAV(s + 1, (s + 1) & 1); CP_COMMIT(); }
        compute(s & 1);
    }

#pragma unroll
    for (int mf = 0; mf < 2; mf++)
#pragma unroll
        for (int nf = 0; nf < 4; nf++) {
            float* cc = acc[mf * 4 + nf];
            int col = wn + nf * 8 + (lane & 3) * 2;
#pragma unroll
            for (int rp = 0; rp < 2; rp++) {
                int mrow = bm + wm + mf * 16 + (lane >> 2) + rp * 8;
                *(float2*)(g_X + ((size_t)(b * 512 + mrow)) * 512 + h * 64 + col) =
                    make_float2(cc[rp * 2], cc[rp * 2 + 1]);
            }
        }
}

// ===================== parallel norm01 stats (exact int64 atomics) =================
__global__ __launch_bounds__(256) void stats_kernel(
    const int* __restrict__ sgap, const int* __restrict__ pcount)
{
    __shared__ long long sh[32];
    int idx = blockIdx.x * 256 + threadIdx.x;
    long long a = sgap[idx], b = pcount[idx];
    long long s0 = a, q0 = a * a, s1 = b, q1 = b * b;
#pragma unroll
    for (int off = 16; off; off >>= 1) {
        s0 += __shfl_xor_sync(0xffffffffu, s0, off);
        q0 += __shfl_xor_sync(0xffffffffu, q0, off);
        s1 += __shfl_xor_sync(0xffffffffu, s1, off);
        q1 += __shfl_xor_sync(0xffffffffu, q1, off);
    }
    int wd = threadIdx.x >> 5, ln = threadIdx.x & 31;
    if (ln == 0) { sh[wd] = s0; sh[8+wd] = q0; sh[16+wd] = s1; sh[24+wd] = q1; }
    __syncthreads();
    if (threadIdx.x == 0) {
        long long S0=0,Q0=0,S1=0,Q1=0;
        for (int i = 0; i < 8; i++) { S0+=sh[i]; Q0+=sh[8+i]; S1+=sh[16+i]; Q1+=sh[24+i]; }
        atomicAdd(&g_sacc[0], (unsigned long long)S0);
        atomicAdd(&g_sacc[1], (unsigned long long)Q0);
        atomicAdd(&g_sacc[2], (unsigned long long)S1);
        atomicAdd(&g_sacc[3], (unsigned long long)Q1);
    }
}

// ===================== interference hidden layer (stats finalized inline) ==========
__global__ __launch_bounds__(256) void hidden_kernel(
    const int* __restrict__ sgap, const int* __restrict__ pcount,
    const float* __restrict__ Wi1, const float* __restrict__ bi1)
{
    float n = (float)MTOT;
    float S0 = (float)(long long)g_sacc[0], Q0 = (float)(long long)g_sacc[1];
    float S1 = (float)(long long)g_sacc[2], Q1 = (float)(long long)g_sacc[3];
    float m0 = S0 / n, m1 = S1 / n;
    float v0 = (Q0 - n*m0*m0) / (n - 1.f);
    float v1 = (Q1 - n*m1*m1) / (n - 1.f);
    float inv0 = 1.f / (sqrtf(fmaxf(v0, 0.f)) + 1e-6f);
    float inv1 = 1.f / (sqrtf(fmaxf(v1, 0.f)) + 1e-6f);

    int idx = blockIdx.x * 256 + threadIdx.x;
    int r = idx >> 7, mcol = idx & 127;
    float ii0 = 0.5f * (tanhf(((float)sgap[r]   - m0) * inv0) + 1.f);
    float ii1 = 0.5f * (tanhf(((float)pcount[r] - m1) * inv1) + 1.f);
    float hv = ii0 * Wi1[2*mcol] + ii1 * Wi1[2*mcol + 1] + bi1[mcol];
    g_H[idx] = fmaxf(hv, 0.f);
}

// ===================== per-row LN stats (mean, rstd) of g_Y ========================
__global__ __launch_bounds__(256) void rowstats_kernel()
{
    int r = blockIdx.x * 8 + (threadIdx.x >> 5);
    int lane = threadIdx.x & 31;
    const float4* row = (const float4*)(g_Y + (size_t)r * DM);
    float s = 0.f, q = 0.f;
#pragma unroll
    for (int c = 0; c < 4; c++) {
        float4 v = row[lane + 32 * c];
        s += v.x + v.y + v.z + v.w;
        q += v.x*v.x + v.y*v.y + v.z*v.z + v.w*v.w;
    }
#pragma unroll
    for (int off = 16; off; off >>= 1) {
        s += __shfl_xor_sync(0xffffffffu, s, off);
        q += __shfl_xor_sync(0xffffffffu, q, off);
    }
    if (lane == 0) {
        float mu  = s * (1.f / 512.f);
        float var = q * (1.f / 512.f) - mu * mu;
        g_rowst[r] = make_float2(mu, rsqrtf(var + 1e-5f));
    }
}

// ===================== launcher =====================
extern "C" void kernel_launch(void* const* d_in, const int* in_sizes, int n_in,
                              void* d_out, int out_size)
{
    const float* q      = (const float*)d_in[0];
    const float* k      = (const float*)d_in[1];
    const float* v      = (const float*)d_in[2];
    const int*   sgap   = (const int*)d_in[3];
    const int*   pcount = (const int*)d_in[4];
    const float* Wq = (const float*)d_in[5];  const float* bq = (const float*)d_in[6];
    const float* Wk = (const float*)d_in[7];  const float* bk = (const float*)d_in[8];
    const float* Wv = (const float*)d_in[9];  const float* bv = (const float*)d_in[10];
    const float* Wo = (const float*)d_in[11]; const float* bo = (const float*)d_in[12];
    const float* gammas = (const float*)d_in[13];
    const float* ln_g = (const float*)d_in[14]; const float* ln_b = (const float*)d_in[15];
    const float* Wi1 = (const float*)d_in[16];  const float* bi1 = (const float*)d_in[17];
    const float* Wi2 = (const float*)d_in[18];  const float* bi2 = (const float*)d_in[19];
    const float* iscale = (const float*)d_in[20];
    float* out = (float*)d_out;

    float *X, *Y, *Hb;
    __nv_bfloat16 *Qb, *Kb, *Vtb;
    unsigned char* Wpk;
    cudaGetSymbolAddress((void**)&X,   g_X);
    cudaGetSymbolAddress((void**)&Y,   g_Y);
    cudaGetSymbolAddress((void**)&Hb,  g_H);
    cudaGetSymbolAddress((void**)&Qb,  g_Qb);
    cudaGetSymbolAddress((void**)&Kb,  g_Kb);
    cudaGetSymbolAddress((void**)&Vtb, g_Vtb);
    cudaGetSymbolAddress((void**)&Wpk, g_Wpk);

    cudaFuncSetAttribute(tgemm_kernel<3>, cudaFuncAttributeMaxDynamicSharedMemorySize, TG2_SMEM);
    cudaFuncSetAttribute(tgemm_kernel<4>, cudaFuncAttributeMaxDynamicSharedMemorySize, TG2_SMEM);
    cudaFuncSetAttribute(tgemm_kernel<5>, cudaFuncAttributeMaxDynamicSharedMemorySize, TG2_SMEM);
    cudaFuncSetAttribute(tgemm_kernel<6>, cudaFuncAttributeMaxDynamicSharedMemorySize, TG2_SMEM);
    cudaFuncSetAttribute(tgemm_kernel<7>, cudaFuncAttributeMaxDynamicSharedMemorySize, TG2_SMEM);
    cudaFuncSetAttribute(qk_kernel, cudaFuncAttributeMaxDynamicSharedMemorySize, SK_SMEM);
    cudaFuncSetAttribute(av_kernel, cudaFuncAttributeMaxDynamicSharedMemorySize, AV_SMEM);

    wconv_all<<<2176, 256>>>(Wq, Wk, Wv, Wo, Wi2, Wpk);
    stats_kernel<<<32, 256>>>(sgap, pcount);

    dim3 gg(4, 64);
    tgemm_kernel<4><<<gg, 256, TG2_SMEM>>>(q, Wpk + 0u*1048576u, bq, nullptr, Qb,  DM, DM, 262144, nullptr, nullptr, nullptr, nullptr);
    tgemm_kernel<5><<<gg, 256, TG2_SMEM>>>(k, Wpk + 1u*1048576u, bk, nullptr, Kb,  DM, DM, 262144, nullptr, nullptr, nullptr, nullptr);
    tgemm_kernel<6><<<gg, 256, TG2_SMEM>>>(v, Wpk + 2u*1048576u, bv, nullptr, Vtb, DM, DM, 262144, nullptr, nullptr, nullptr, nullptr);

    qk_kernel<<<dim3(4, 4, 128), 256, SK_SMEM>>>();
    row_kernel<<<dim3(64, 128), 256>>>(gammas);
    av_kernel<<<dim3(4, 128), 256, AV_SMEM>>>();

    hidden_kernel<<<(MTOT*128)/256, 256>>>(sgap, pcount, Wi1, bi1);
    tgemm_kernel<3><<<gg, 256, TG2_SMEM>>>(Hb, Wpk + 4u*1048576u, bi2, Y, nullptr, DM, 128, 65536, X, iscale, nullptr, nullptr);

    rowstats_kernel<<<MTOT/8, 256>>>();

    tgemm_kernel<7><<<gg, 256, TG2_SMEM>>>(Y, Wpk + 3u*1048576u, bo, out, nullptr, DM, DM, 262144, nullptr, nullptr, ln_g, ln_b);
}

// round 7
// speedup vs baseline: 1.0483x; 1.0483x over previous
#include <cuda_runtime.h>
#include <cuda_bf16.h>
#include <math.h>
#include <cstdint>

#define BSZ 16
#define SEQ 512
#define DM  512
#define NH  8
#define DKH 64
#define MTOT (BSZ*SEQ)
#define NEG_INF (__int_as_float(0xff800000))
#define QKVPLN (128*512*64)       // 4194304
#define APLN (128u*512u*512u)     // 33554432

// ===================== scratch =====================
__device__ __nv_bfloat16 g_Ain[3u*2u*4194304u];  // q,k,v input planes
__device__ __nv_bfloat16 g_Qb [2*QKVPLN];        // [b,h,s,d] hi|lo (x1/8)
__device__ __nv_bfloat16 g_Kb [2*QKVPLN];
__device__ __nv_bfloat16 g_Vtb[2*QKVPLN];        // [b,h,d,s]
__device__ float         g_S  [APLN];
__device__ __nv_bfloat16 g_A  [2*APLN];
__device__ float g_X [MTOT*DM];
__device__ float g_Y [MTOT*DM];
__device__ __nv_bfloat16 g_Yb[2u*4194304u];
__device__ __nv_bfloat16 g_Hb[2u*1048576u];
__device__ unsigned long long g_sacc[4];
__device__ unsigned char g_Wpk[5u*1024u*1024u];

// ===================== asm helpers =====================
__device__ __forceinline__ uint32_t smem_to_u32(const void* p) {
    uint32_t a;
    asm("{ .reg .u64 t; cvta.to.shared.u64 t, %1; cvt.u32.u64 %0, t; }" : "=r"(a) : "l"(p));
    return a;
}
__device__ __forceinline__ void ldsm4(uint32_t* r, uint32_t addr) {
    asm volatile("ldmatrix.sync.aligned.m8n8.x4.shared.b16 {%0,%1,%2,%3}, [%4];"
        : "=r"(r[0]), "=r"(r[1]), "=r"(r[2]), "=r"(r[3]) : "r"(addr));
}
__device__ __forceinline__ void mma16816(float* c, const uint32_t* a, const uint32_t* b) {
    asm volatile("mma.sync.aligned.m16n8k16.row.col.f32.bf16.bf16.f32 "
        "{%0,%1,%2,%3}, {%4,%5,%6,%7}, {%8,%9}, {%0,%1,%2,%3};"
        : "+f"(c[0]), "+f"(c[1]), "+f"(c[2]), "+f"(c[3])
        : "r"(a[0]), "r"(a[1]), "r"(a[2]), "r"(a[3]), "r"(b[0]), "r"(b[1]));
}
__device__ __forceinline__ uint32_t pack_hi(float x, float y, float& lx, float& ly) {
    __nv_bfloat162 h = __floats2bfloat162_rn(x, y);
    lx = x - __bfloat162float(h.x);
    ly = y - __bfloat162float(h.y);
    return *reinterpret_cast<uint32_t*>(&h);
}
__device__ __forceinline__ uint32_t pack_lo(float lx, float ly) {
    __nv_bfloat162 l = __floats2bfloat162_rn(lx, ly);
    return *reinterpret_cast<uint32_t*>(&l);
}
#define CP_ASYNC16(dst, src) \
    asm volatile("cp.async.cg.shared.global [%0], [%1], 16;" :: "r"(dst), "l"(src))
#define CP_COMMIT() asm volatile("cp.async.commit_group;" ::: "memory")
#define CP_WAIT0()  asm volatile("cp.async.wait_group 0;"  ::: "memory")
#define CP_WAIT1()  asm volatile("cp.async.wait_group 1;"  ::: "memory")

// ===================== weight pre-split =====================
__global__ __launch_bounds__(256) void wconv_all(
    const float* __restrict__ Wq, const float* __restrict__ Wk,
    const float* __restrict__ Wv, const float* __restrict__ Wo,
    const float* __restrict__ Wi2, unsigned char* __restrict__ dst)
{
    if (blockIdx.x == 0 && threadIdx.x < 4) g_sacc[threadIdx.x] = 0ull;
    int bb = blockIdx.x;
    const float* W; unsigned char* d; int K;
    if      (bb < 512)  { W = Wq;  d = dst;              K = 512; }
    else if (bb < 1024) { W = Wk;  d = dst + 1048576u;   K = 512; bb -= 512; }
    else if (bb < 1536) { W = Wv;  d = dst + 2097152u;   K = 512; bb -= 1024; }
    else if (bb < 2048) { W = Wo;  d = dst + 3145728u;   K = 512; bb -= 1536; }
    else                { W = Wi2; d = dst + 4194304u;   K = 128; bb -= 2048; }
    int NK = (K == 512) ? 262144 : 65536;
    int idx = bb * 256 + threadIdx.x;
    int halfK = K >> 1;
    int n = idx / halfK;
    int k = (idx - n * halfK) * 2;
    float x0 = W[(size_t)n * K + k];
    float x1 = W[(size_t)n * K + k + 1];
    float lx, ly;
    uint32_t hp = pack_hi(x0, x1, lx, ly);
    uint32_t lp = pack_lo(lx, ly);
    *(uint32_t*)(d + (size_t)(n * K + k) * 2)                  = hp;
    *(uint32_t*)(d + (size_t)NK * 2 + (size_t)(n * K + k) * 2) = lp;
}

// ===================== input activation pre-split =====================
__global__ __launch_bounds__(256) void aconv_kernel(
    const float* __restrict__ q, const float* __restrict__ k, const float* __restrict__ v)
{
    const float* src = blockIdx.y == 0 ? q : blockIdx.y == 1 ? k : v;
    __nv_bfloat16* dst = g_Ain + (size_t)blockIdx.y * 8388608u;
    size_t e = ((size_t)blockIdx.x * 256 + threadIdx.x) * 4;
    float4 x = *(const float4*)(src + e);
    float l0, l1, l2, l3;
    uint2 hp; hp.x = pack_hi(x.x, x.y, l0, l1); hp.y = pack_hi(x.z, x.w, l2, l3);
    uint2 lp; lp.x = pack_lo(l0, l1);           lp.y = pack_lo(l2, l3);
    *(uint2*)(dst + e)            = hp;
    *(uint2*)(dst + 4194304u + e) = lp;
}

// ===================== unified pre-packed GEMM (mma.sync, bf16 3-term) =============
// mode = mode0 + blockIdx.z. mode 0: plain fp32 C. 3: g_Y = g_X + scale*(acc+bias).
// 4: Q planes x1/8. 5: K planes. 6: V^T planes.
#define PG_BUF 40960
#define PG_SMEM 81920

__global__ __launch_bounds__(256, 2) void pgemm_kernel(
    const __nv_bfloat16* __restrict__ Abase, long APL,
    const unsigned char* __restrict__ Bpk0, int K, int NK, int mode0,
    const float* __restrict__ b0, const float* __restrict__ b1, const float* __restrict__ b2,
    float* __restrict__ C, const float* __restrict__ scale)
{
    extern __shared__ char sm[];
    const uint32_t sbase = smem_to_u32(sm);
    const int tid = threadIdx.x, wid = tid >> 5, lane = tid & 31;
    const int bm = blockIdx.y * 128, bn = blockIdx.x * 128;
    const int z = blockIdx.z;
    const int mode = mode0 + z;
    const __nv_bfloat16* Abf = Abase + (size_t)z * 2 * APL;
    const unsigned char* Bpk = Bpk0 + (size_t)z * 1048576u;
    const float* bias = (z == 0) ? b0 : (z == 1) ? b1 : b2;
    const int S = K >> 5;

    float acc[16][4];
#pragma unroll
    for (int i = 0; i < 16; i++)
#pragma unroll
        for (int j = 0; j < 4; j++) acc[i][j] = 0.f;

    auto issue = [&](int s, int buf) {
        uint32_t base = sbase + buf * PG_BUF;
        int k0 = s * 32;
#pragma unroll
        for (int it = 0; it < 4; it++) {
            int idx = it * 256 + tid;
            int pl = idx >> 9, r = (idx >> 2) & 127, c = idx & 3;
            const unsigned char* asrc = (const unsigned char*)(Abf + (size_t)pl * APL +
                                        (size_t)(bm + r) * K + k0 + c * 8);
            CP_ASYNC16(base + pl * 10240 + r * 80 + c * 16, asrc);
            const unsigned char* bsrc = Bpk + (size_t)pl * NK * 2 +
                                        ((size_t)(bn + r) * K + k0 + c * 8) * 2;
            CP_ASYNC16(base + 20480 + pl * 10240 + r * 80 + c * 16, bsrc);
        }
    };

    const int wm = (wid >> 2) * 64, wn = (wid & 3) * 32;
    const int aoff   = (lane & 15) * 80 + (lane >> 4) * 16;
    const int boff_n = ((lane >> 4) << 3) + (lane & 7);
    const int bsel   = ((lane >> 3) & 1) * 16;

    auto compute = [&](int buf) {
        uint32_t Ab = sbase + buf * PG_BUF;
        uint32_t Bb = Ab + 20480;
#pragma unroll
        for (int kh = 0; kh < 2; kh++) {
            uint32_t bh[8], bl[8], a[16];
#pragma unroll
            for (int nf2 = 0; nf2 < 2; nf2++) {
                uint32_t baddr = Bb + (wn + nf2 * 16 + boff_n) * 80 + kh * 32 + bsel;
                ldsm4(bh + nf2 * 4, baddr);
                ldsm4(bl + nf2 * 4, baddr + 10240);
            }
#pragma unroll
            for (int mf = 0; mf < 4; mf++)
                ldsm4(a + mf * 4, Ab + (wm + mf * 16) * 80 + kh * 32 + aoff);
#pragma unroll
            for (int mf = 0; mf < 4; mf++)
#pragma unroll
                for (int nf = 0; nf < 4; nf++)
                    mma16816(acc[mf * 4 + nf], a + mf * 4, bh + nf * 2);
#pragma unroll
            for (int mf = 0; mf < 4; mf++)
#pragma unroll
                for (int nf = 0; nf < 4; nf++)
                    mma16816(acc[mf * 4 + nf], a + mf * 4, bl + nf * 2);
#pragma unroll
            for (int mf = 0; mf < 4; mf++)
                ldsm4(a + mf * 4, Ab + 10240 + (wm + mf * 16) * 80 + kh * 32 + aoff);
#pragma unroll
            for (int mf = 0; mf < 4; mf++)
#pragma unroll
                for (int nf = 0; nf < 4; nf++)
                    mma16816(acc[mf * 4 + nf], a + mf * 4, bh + nf * 2);
        }
    };

    issue(0, 0); CP_COMMIT();
    for (int s = 0; s < S; s++) {
        if (s + 1 < S) { issue(s + 1, (s + 1) & 1); CP_COMMIT(); CP_WAIT1(); }
        else           { CP_WAIT0(); }
        __syncthreads();
        compute(s & 1);
        __syncthreads();
    }

    const float isc = (mode == 3) ? scale[0] : 0.f;
#pragma unroll
    for (int mf = 0; mf < 4; mf++) {
#pragma unroll
        for (int nf = 0; nf < 4; nf++) {
            float* cc = acc[mf * 4 + nf];
            int col = bn + wn + nf * 8 + (lane & 3) * 2;
            float bv0 = bias[col], bv1 = bias[col + 1];
#pragma unroll
            for (int rp = 0; rp < 2; rp++) {
                int m = bm + wm + mf * 16 + (lane >> 2) + rp * 8;
                float v0 = cc[rp * 2 + 0] + bv0;
                float v1 = cc[rp * 2 + 1] + bv1;
                if (mode == 0) {
                    *(float2*)(C + (size_t)m * DM + col) = make_float2(v0, v1);
                } else if (mode == 3) {
                    const float* ad = g_X + (size_t)m * DM + col;
                    *(float2*)(g_Y + (size_t)m * DM + col) =
                        make_float2(ad[0] + isc * v0, ad[1] + isc * v1);
                } else if (mode == 4 || mode == 5) {
                    if (mode == 4) { v0 *= 0.125f; v1 *= 0.125f; }
                    int bb = m >> 9, si = m & 511, hh = col >> 6, d = col & 63;
                    size_t idx = (((size_t)(bb * NH + hh)) * SEQ + si) * DKH + d;
                    __nv_bfloat16* Cb = (mode == 4) ? g_Qb : g_Kb;
                    float l0, l1;
                    uint32_t hp = pack_hi(v0, v1, l0, l1);
                    uint32_t lp = pack_lo(l0, l1);
                    *(uint32_t*)&Cb[idx]          = hp;
                    *(uint32_t*)&Cb[idx + QKVPLN] = lp;
                } else {  // mode 6: V^T planes
                    int bb = m >> 9, si = m & 511, hh = col >> 6, d = col & 63;
                    size_t i0 = (((size_t)(bb * NH + hh)) * DKH + d) * SEQ + si;
                    __nv_bfloat16 h0 = __float2bfloat16(v0);
                    __nv_bfloat16 h1 = __float2bfloat16(v1);
                    g_Vtb[i0]                = h0;
                    g_Vtb[i0 + QKVPLN]       = __float2bfloat16(v0 - __bfloat162float(h0));
                    g_Vtb[i0 + SEQ]          = h1;
                    g_Vtb[i0 + SEQ + QKVPLN] = __float2bfloat16(v1 - __bfloat162float(h1));
                }
            }
        }
    }
}

// ===================== QK^T batched GEMM (causal tile skip) ========================
#define SK_SMEM 73728

__global__ __launch_bounds__(256, 2) void qk_kernel()
{
    if (blockIdx.x > blockIdx.y) return;
    extern __shared__ char sm[];
    const uint32_t sbase = smem_to_u32(sm);
    const int bn = blockIdx.x * 128, bm = blockIdx.y * 128;
    const int bh = blockIdx.z;
    const int tid = threadIdx.x, wid = tid >> 5, lane = tid & 31;

#pragma unroll
    for (int pl = 0; pl < 2; pl++) {
        const unsigned char* qsrc = (const unsigned char*)(g_Qb + (size_t)pl * QKVPLN + ((size_t)bh * 512 + bm) * 64);
        const unsigned char* ksrc = (const unsigned char*)(g_Kb + (size_t)pl * QKVPLN + ((size_t)bh * 512 + bn) * 64);
        uint32_t qdst = sbase + pl * 18432;
        uint32_t kdst = sbase + 36864 + pl * 18432;
#pragma unroll
        for (int it = 0; it < 4; it++) {
            int idx = it * 256 + tid;
            int r = idx >> 3, c = idx & 7;
            CP_ASYNC16(qdst + r * 144 + c * 16, qsrc + (size_t)r * 128 + c * 16);
            CP_ASYNC16(kdst + r * 144 + c * 16, ksrc + (size_t)r * 128 + c * 16);
        }
    }
    CP_COMMIT(); CP_WAIT0();
    __syncthreads();

    const int wm = (wid >> 2) * 64, wn = (wid & 3) * 32;
    const int aoff   = (lane & 15) * 144 + (lane >> 4) * 16;
    const int boff_n = ((lane >> 4) << 3) + (lane & 7);
    const int bsel   = ((lane >> 3) & 1) * 16;
    const uint32_t QHI = sbase, QLO = sbase + 18432;
    const uint32_t KHI = sbase + 36864;

    float acc[16][4];
#pragma unroll
    for (int i = 0; i < 16; i++)
#pragma unroll
        for (int j = 0; j < 4; j++) acc[i][j] = 0.f;

#pragma unroll
    for (int kh = 0; kh < 4; kh++) {
        uint32_t bh_[8], bl_[8], a[16];
#pragma unroll
        for (int nf2 = 0; nf2 < 2; nf2++) {
            uint32_t baddr = KHI + (wn + nf2 * 16 + boff_n) * 144 + kh * 32 + bsel;
            ldsm4(bh_ + nf2 * 4, baddr);
            ldsm4(bl_ + nf2 * 4, baddr + 18432);
        }
#pragma unroll
        for (int mf = 0; mf < 4; mf++)
            ldsm4(a + mf * 4, QHI + (wm + mf * 16) * 144 + kh * 32 + aoff);
#pragma unroll
        for (int mf = 0; mf < 4; mf++)
#pragma unroll
            for (int nf = 0; nf < 4; nf++)
                mma16816(acc[mf * 4 + nf], a + mf * 4, bh_ + nf * 2);
#pragma unroll
        for (int mf = 0; mf < 4; mf++)
#pragma unroll
            for (int nf = 0; nf < 4; nf++)
                mma16816(acc[mf * 4 + nf], a + mf * 4, bl_ + nf * 2);
#pragma unroll
        for (int mf = 0; mf < 4; mf++)
            ldsm4(a + mf * 4, QLO + (wm + mf * 16) * 144 + kh * 32 + aoff);
#pragma unroll
        for (int mf = 0; mf < 4; mf++)
#pragma unroll
            for (int nf = 0; nf < 4; nf++)
                mma16816(acc[mf * 4 + nf], a + mf * 4, bh_ + nf * 2);
    }

    float* Sp = g_S + (size_t)bh * 512 * 512;
#pragma unroll
    for (int mf = 0; mf < 4; mf++)
#pragma unroll
        for (int nf = 0; nf < 4; nf++) {
            float* cc = acc[mf * 4 + nf];
            int col = bn + wn + nf * 8 + (lane & 3) * 2;
#pragma unroll
            for (int rp = 0; rp < 2; rp++) {
                int m = bm + wm + mf * 16 + (lane >> 2) + rp * 8;
                *(float2*)(Sp + (size_t)m * 512 + col) =
                    make_float2(cc[rp * 2], cc[rp * 2 + 1]);
            }
        }
}

// ===================== row kernel (causal-truncated tiles) =========================
__global__ __launch_bounds__(256) void row_kernel(const float* __restrict__ gammas)
{
    const int bh = blockIdx.y, h = bh & 7;
    const int wid = threadIdx.x >> 5, lane = threadIdx.x & 31;
    const int i = blockIdx.x * 8 + wid;
    const int Ti = i >> 7;
    __nv_bfloat16* Ahi = g_A + ((size_t)bh * 512 + i) * 512;

    if (i == 0) {
        uint2 z = make_uint2(0u, 0u);
        int j0 = 4 * lane;
        *(uint2*)(Ahi + j0)        = z;
        *(uint2*)(Ahi + APLN + j0) = z;
        return;
    }

    float gv = gammas[h];
    float gam = -(fmaxf(gv, 0.f) + log1pf(__expf(-fabsf(gv))));

    const float4* Srow = (const float4*)(g_S + ((size_t)bh * 512 + i) * 512);
    float sc[4][4], e[4][4], ls[4];
#pragma unroll
    for (int t = 0; t < 4; t++) {
        if (t > Ti) { ls[t] = 0.f; continue; }
        float4 sv = Srow[lane + 32 * t];
        int j0 = 4 * (lane + 32 * t);
        sc[t][0] = (j0 + 0 < i) ? sv.x : NEG_INF;
        sc[t][1] = (j0 + 1 < i) ? sv.y : NEG_INF;
        sc[t][2] = (j0 + 2 < i) ? sv.z : NEG_INF;
        sc[t][3] = (j0 + 3 < i) ? sv.w : NEG_INF;
    }

    float m = NEG_INF;
#pragma unroll
    for (int t = 0; t < 4; t++) {
        if (t > Ti) break;
#pragma unroll
        for (int l = 0; l < 4; l++) m = fmaxf(m, sc[t][l]);
    }
#pragma unroll
    for (int off = 16; off; off >>= 1)
        m = fmaxf(m, __shfl_xor_sync(0xffffffffu, m, off));

#pragma unroll
    for (int t = 0; t < 4; t++) {
        if (t > Ti) break;
        ls[t] = 0.f;
#pragma unroll
        for (int l = 0; l < 4; l++) { e[t][l] = __expf(sc[t][l] - m); ls[t] += e[t][l]; }
    }
    float excl[4], tot[4];
#pragma unroll
    for (int t = 0; t < 4; t++) {
        if (t > Ti) break;
        float x = ls[t];
#pragma unroll
        for (int off = 1; off < 32; off <<= 1) {
            float y = __shfl_up_sync(0xffffffffu, x, off);
            if (lane >= off) x += y;
        }
        excl[t] = x - ls[t];
        tot[t]  = __shfl_sync(0xffffffffu, x, 31);
    }
    float baseA[4], T = 0.f;
#pragma unroll
    for (int t = 0; t < 4; t++) {
        if (t > Ti) break;
        baseA[t] = T; T += tot[t];
    }
    float invT = 1.f / T;

#pragma unroll
    for (int t = 0; t < 4; t++) {
        if (t > Ti) break;
        float run = baseA[t] + excl[t];
#pragma unroll
        for (int l = 0; l < 4; l++) {
            run += e[t][l];
            int j = 4 * lane + 128 * t + l;
            float suf  = fmaxf(T - run, 0.f);
            float dist = sqrtf(fmaxf(suf * invT * (float)(i - j), 0.f));
            float tmp  = __expf(dist * gam);
            tmp = fminf(fmaxf(tmp, 1e-5f), 1e5f);
            sc[t][l] = (j < i) ? sc[t][l] * tmp : NEG_INF;
        }
    }

    float m2 = NEG_INF;
#pragma unroll
    for (int t = 0; t < 4; t++) {
        if (t > Ti) break;
#pragma unroll
        for (int l = 0; l < 4; l++) m2 = fmaxf(m2, sc[t][l]);
    }
#pragma unroll
    for (int off = 16; off; off >>= 1)
        m2 = fmaxf(m2, __shfl_xor_sync(0xffffffffu, m2, off));
    float Z = 0.f;
#pragma unroll
    for (int t = 0; t < 4; t++) {
        if (t > Ti) break;
#pragma unroll
        for (int l = 0; l < 4; l++) { e[t][l] = __expf(sc[t][l] - m2); Z += e[t][l]; }
    }
#pragma unroll
    for (int off = 16; off; off >>= 1)
        Z += __shfl_xor_sync(0xffffffffu, Z, off);
    float invZ = 1.f / Z;

#pragma unroll
    for (int t = 0; t < 4; t++) {
        if (t > Ti) break;
        float a0 = e[t][0] * invZ, a1 = e[t][1] * invZ;
        float a2 = e[t][2] * invZ, a3 = e[t][3] * invZ;
        float l0, l1, l2, l3;
        uint2 hp; hp.x = pack_hi(a0, a1, l0, l1); hp.y = pack_hi(a2, a3, l2, l3);
        uint2 lp; lp.x = pack_lo(l0, l1);         lp.y = pack_lo(l2, l3);
        int j0 = 4 * (lane + 32 * t);
        *(uint2*)(Ahi + j0)        = hp;
        *(uint2*)(Ahi + APLN + j0) = lp;
    }
}

// ===================== AV batched GEMM (causal K-limit) ===========================
#define AV_BUF 30720
#define AV_SMEM 61440

__global__ __launch_bounds__(256, 2) void av_kernel()
{
    extern __shared__ char sm[];
    const uint32_t sbase = smem_to_u32(sm);
    const int bm = blockIdx.x * 128;
    const int bh = blockIdx.y;
    const int b = bh >> 3, h = bh & 7;
    const int tid = threadIdx.x, wid = tid >> 5, lane = tid & 31;
    const int nst = (bm + 128) >> 5;

    float acc[8][4];
#pragma unroll
    for (int i = 0; i < 8; i++)
#pragma unroll
        for (int j = 0; j < 4; j++) acc[i][j] = 0.f;

    auto issueAV = [&](int s, int buf) {
        uint32_t base = sbase + buf * AV_BUF;
#pragma unroll
        for (int it = 0; it < 4; it++) {
            int idx = it * 256 + tid;
            int pl = idx >> 9, r = (idx >> 2) & 127, c = idx & 3;
            const unsigned char* src = (const unsigned char*)(g_A + (size_t)pl * APLN +
                ((size_t)bh * 512 + bm + r) * 512 + s * 32 + c * 8);
            CP_ASYNC16(base + pl * 10240 + r * 80 + c * 16, src);
        }
#pragma unroll
        for (int it = 0; it < 2; it++) {
            int idx = it * 256 + tid;
            int pl = idx >> 8, d = (idx >> 2) & 63, c = idx & 3;
            const unsigned char* src = (const unsigned char*)(g_Vtb + (size_t)pl * QKVPLN +
                ((size_t)bh * 64 + d) * 512 + s * 32 + c * 8);
            CP_ASYNC16(base + 20480 + pl * 5120 + d * 80 + c * 16, src);
        }
    };

    const int wm = (wid >> 1) * 32, wn = (wid & 1) * 32;
    const int aoff   = (lane & 15) * 80 + (lane >> 4) * 16;
    const int boff_n = ((lane >> 4) << 3) + (lane & 7);
    const int bsel   = ((lane >> 3) & 1) * 16;

    auto compute = [&](int buf) {
        uint32_t Ab = sbase + buf * AV_BUF;
        uint32_t Vb = Ab + 20480;
#pragma unroll
        for (int kh = 0; kh < 2; kh++) {
            uint32_t bh_[8], bl_[8], a[8];
#pragma unroll
            for (int nf2 = 0; nf2 < 2; nf2++) {
                uint32_t baddr = Vb + (wn + nf2 * 16 + boff_n) * 80 + kh * 32 + bsel;
                ldsm4(bh_ + nf2 * 4, baddr);
                ldsm4(bl_ + nf2 * 4, baddr + 5120);
            }
#pragma unroll
            for (int mf = 0; mf < 2; mf++)
                ldsm4(a + mf * 4, Ab + (wm + mf * 16) * 80 + kh * 32 + aoff);
#pragma unroll
            for (int mf = 0; mf < 2; mf++)
#pragma unroll
                for (int nf = 0; nf < 4; nf++)
                    mma16816(acc[mf * 4 + nf], a + mf * 4, bh_ + nf * 2);
#pragma unroll
            for (int mf = 0; mf < 2; mf++)
#pragma unroll
                for (int nf = 0; nf < 4; nf++)
                    mma16816(acc[mf * 4 + nf], a + mf * 4, bl_ + nf * 2);
#pragma unroll
            for (int mf = 0; mf < 2; mf++)
                ldsm4(a + mf * 4, Ab + 10240 + (wm + mf * 16) * 80 + kh * 32 + aoff);
#pragma unroll
            for (int mf = 0; mf < 2; mf++)
#pragma unroll
                for (int nf = 0; nf < 4; nf++)
                    mma16816(acc[mf * 4 + nf], a + mf * 4, bh_ + nf * 2);
        }
    };

    issueAV(0, 0); CP_COMMIT();
    for (int s = 0; s < nst; s++) {
        if (s + 1 < nst) { issueAV(s + 1, (s + 1) & 1); CP_COMMIT(); CP_WAIT1(); }
        else             { CP_WAIT0(); }
        __syncthreads();
        compute(s & 1);
        __syncthreads();
    }

#pragma unroll
    for (int mf = 0; mf < 2; mf++)
#pragma unroll
        for (int nf = 0; nf < 4; nf++) {
            float* cc = acc[mf * 4 + nf];
            int col = wn + nf * 8 + (lane & 3) * 2;
#pragma unroll
            for (int rp = 0; rp < 2; rp++) {
                int mrow = bm + wm + mf * 16 + (lane >> 2) + rp * 8;
                *(float2*)(g_X + ((size_t)(b * 512 + mrow)) * 512 + h * 64 + col) =
                    make_float2(cc[rp * 2], cc[rp * 2 + 1]);
            }
        }
}

// ===================== parallel norm01 stats =====================
__global__ __launch_bounds__(256) void stats_kernel(
    const int* __restrict__ sgap, const int* __restrict__ pcount)
{
    __shared__ long long sh[32];
    int idx = blockIdx.x * 256 + threadIdx.x;
    long long a = sgap[idx], b = pcount[idx];
    long long s0 = a, q0 = a * a, s1 = b, q1 = b * b;
#pragma unroll
    for (int off = 16; off; off >>= 1) {
        s0 += __shfl_xor_sync(0xffffffffu, s0, off);
        q0 += __shfl_xor_sync(0xffffffffu, q0, off);
        s1 += __shfl_xor_sync(0xffffffffu, s1, off);
        q1 += __shfl_xor_sync(0xffffffffu, q1, off);
    }
    int wd = threadIdx.x >> 5, ln = threadIdx.x & 31;
    if (ln == 0) { sh[wd] = s0; sh[8+wd] = q0; sh[16+wd] = s1; sh[24+wd] = q1; }
    __syncthreads();
    if (threadIdx.x == 0) {
        long long S0=0,Q0=0,S1=0,Q1=0;
        for (int i = 0; i < 8; i++) { S0+=sh[i]; Q0+=sh[8+i]; S1+=sh[16+i]; Q1+=sh[24+i]; }
        atomicAdd(&g_sacc[0], (unsigned long long)S0);
        atomicAdd(&g_sacc[1], (unsigned long long)Q0);
        atomicAdd(&g_sacc[2], (unsigned long long)S1);
        atomicAdd(&g_sacc[3], (unsigned long long)Q1);
    }
}

// ===================== interference hidden layer -> bf16 planes ===================
__global__ __launch_bounds__(256) void hidden_kernel(
    const int* __restrict__ sgap, const int* __restrict__ pcount,
    const float* __restrict__ Wi1, const float* __restrict__ bi1)
{
    float n = (float)MTOT;
    float S0 = (float)(long long)g_sacc[0], Q0 = (float)(long long)g_sacc[1];
    float S1 = (float)(long long)g_sacc[2], Q1 = (float)(long long)g_sacc[3];
    float m0 = S0 / n, m1 = S1 / n;
    float v0 = (Q0 - n*m0*m0) / (n - 1.f);
    float v1 = (Q1 - n*m1*m1) / (n - 1.f);
    float inv0 = 1.f / (sqrtf(fmaxf(v0, 0.f)) + 1e-6f);
    float inv1 = 1.f / (sqrtf(fmaxf(v1, 0.f)) + 1e-6f);

    int idx = blockIdx.x * 256 + threadIdx.x;   // over 8192*64
    int r = idx >> 6, c2 = (idx & 63) * 2;
    float ii0 = 0.5f * (tanhf(((float)sgap[r]   - m0) * inv0) + 1.f);
    float ii1 = 0.5f * (tanhf(((float)pcount[r] - m1) * inv1) + 1.f);
    float h0 = fmaxf(ii0 * Wi1[2*c2+0] + ii1 * Wi1[2*c2+1] + bi1[c2],     0.f);
    float h1 = fmaxf(ii0 * Wi1[2*c2+2] + ii1 * Wi1[2*c2+3] + bi1[c2+1],   0.f);
    float l0, l1;
    uint32_t hp = pack_hi(h0, h1, l0, l1);
    uint32_t lp = pack_lo(l0, l1);
    *(uint32_t*)&g_Hb[(size_t)r * 128 + c2]             = hp;
    *(uint32_t*)&g_Hb[(size_t)r * 128 + c2 + 1048576u]  = lp;
}

// ===================== LayerNorm + pack to bf16 planes ============================
__global__ __launch_bounds__(256) void ln_pack_kernel(
    const float* __restrict__ gw, const float* __restrict__ bw)
{
    int r = blockIdx.x * 8 + (threadIdx.x >> 5);
    int lane = threadIdx.x & 31;
    const float4* row = (const float4*)(g_Y + (size_t)r * DM);
    float4 xv[4];
    float s = 0.f, q = 0.f;
#pragma unroll
    for (int c = 0; c < 4; c++) {
        xv[c] = row[lane + 32 * c];
        s += xv[c].x + xv[c].y + xv[c].z + xv[c].w;
        q += xv[c].x*xv[c].x + xv[c].y*xv[c].y + xv[c].z*xv[c].z + xv[c].w*xv[c].w;
    }
#pragma unroll
    for (int off = 16; off; off >>= 1) {
        s += __shfl_xor_sync(0xffffffffu, s, off);
        q += __shfl_xor_sync(0xffffffffu, q, off);
    }
    float mu   = s * (1.f / 512.f);
    float rstd = rsqrtf(q * (1.f / 512.f) - mu * mu + 1e-5f);
#pragma unroll
    for (int c = 0; c < 4; c++) {
        float4 g4 = ((const float4*)gw)[lane + 32 * c];
        float4 b4 = ((const float4*)bw)[lane + 32 * c];
        float n0 = (xv[c].x - mu) * rstd * g4.x + b4.x;
        float n1 = (xv[c].y - mu) * rstd * g4.y + b4.y;
        float n2 = (xv[c].z - mu) * rstd * g4.z + b4.z;
        float n3 = (xv[c].w - mu) * rstd * g4.w + b4.w;
        float l0, l1, l2, l3;
        uint2 hp; hp.x = pack_hi(n0, n1, l0, l1); hp.y = pack_hi(n2, n3, l2, l3);
        uint2 lp; lp.x = pack_lo(l0, l1);         lp.y = pack_lo(l2, l3);
        size_t e = (size_t)r * 512 + 4 * (lane + 32 * c);
        *(uint2*)&g_Yb[e]             = hp;
        *(uint2*)&g_Yb[e + 4194304u]  = lp;
    }
}

// ===================== launcher =====================
extern "C" void kernel_launch(void* const* d_in, const int* in_sizes, int n_in,
                              void* d_out, int out_size)
{
    const float* q      = (const float*)d_in[0];
    const float* k      = (const float*)d_in[1];
    const float* v      = (const float*)d_in[2];
    const int*   sgap   = (const int*)d_in[3];
    const int*   pcount = (const int*)d_in[4];
    const float* Wq = (const float*)d_in[5];  const float* bq = (const float*)d_in[6];
    const float* Wk = (const float*)d_in[7];  const float* bk = (const float*)d_in[8];
    const float* Wv = (const float*)d_in[9];  const float* bv = (const float*)d_in[10];
    const float* Wo = (const float*)d_in[11]; const float* bo = (const float*)d_in[12];
    const float* gammas = (const float*)d_in[13];
    const float* ln_g = (const float*)d_in[14]; const float* ln_b = (const float*)d_in[15];
    const float* Wi1 = (const float*)d_in[16];  const float* bi1 = (const float*)d_in[17];
    const float* Wi2 = (const float*)d_in[18];  const float* bi2 = (const float*)d_in[19];
    const float* iscale = (const float*)d_in[20];
    float* out = (float*)d_out;

    __nv_bfloat16 *Ain, *Yb, *Hb;
    unsigned char* Wpk;
    cudaGetSymbolAddress((void**)&Ain, g_Ain);
    cudaGetSymbolAddress((void**)&Yb,  g_Yb);
    cudaGetSymbolAddress((void**)&Hb,  g_Hb);
    cudaGetSymbolAddress((void**)&Wpk, g_Wpk);

    cudaFuncSetAttribute(pgemm_kernel, cudaFuncAttributeMaxDynamicSharedMemorySize, PG_SMEM);
    cudaFuncSetAttribute(qk_kernel, cudaFuncAttributeMaxDynamicSharedMemorySize, SK_SMEM);
    cudaFuncSetAttribute(av_kernel, cudaFuncAttributeMaxDynamicSharedMemorySize, AV_SMEM);

    wconv_all<<<2176, 256>>>(Wq, Wk, Wv, Wo, Wi2, Wpk);
    aconv_kernel<<<dim3(4096, 3), 256>>>(q, k, v);
    stats_kernel<<<32, 256>>>(sgap, pcount);

    // fused QKV projections (z selects input/weight/epilogue)
    pgemm_kernel<<<dim3(4, 64, 3), 256, PG_SMEM>>>(
        Ain, 4194304L, Wpk, 512, 262144, 4, bq, bk, bv, nullptr, nullptr);

    qk_kernel<<<dim3(4, 4, 128), 256, SK_SMEM>>>();
    row_kernel<<<dim3(64, 128), 256>>>(gammas);
    av_kernel<<<dim3(4, 128), 256, AV_SMEM>>>();

    hidden_kernel<<<2048, 256>>>(sgap, pcount, Wi1, bi1);
    // Y = X + iscale*(H @ Wi2^T + bi2)
    pgemm_kernel<<<dim3(4, 64, 1), 256, PG_SMEM>>>(
        Hb, 1048576L, Wpk + 4194304u, 128, 65536, 3, bi2, nullptr, nullptr, nullptr, iscale);

    ln_pack_kernel<<<1024, 256>>>(ln_g, ln_b);

    // out = LN(Y) @ Wo^T + bo
    pgemm_kernel<<<dim3(4, 64, 1), 256, PG_SMEM>>>(
        Yb, 4194304L, Wpk + 3145728u, 512, 262144, 0, bo, nullptr, nullptr, out, nullptr);
}

// round 8
// speedup vs baseline: 1.1840x; 1.1295x over previous
#include <cuda_runtime.h>
#include <cuda_bf16.h>
#include <math.h>
#include <cstdint>

#define BSZ 16
#define SEQ 512
#define DM  512
#define NH  8
#define DKH 64
#define MTOT (BSZ*SEQ)
#define NEG_INF (__int_as_float(0xff800000))
#define QKVPLN 4194304u           // elems per Q/K/Vt plane (8MB)
#define APLN 33554432u            // elems per A plane (64MB)

// ===================== scratch =====================
__device__ __nv_bfloat16 g_Ain[3u*2u*4194304u];  // [z][plane][mt][s][8KB blocks]
__device__ __nv_bfloat16 g_Qb [2*QKVPLN];        // [p][bh][mt][s(2)][8KB]
__device__ __nv_bfloat16 g_Kb [2*QKVPLN];
__device__ __nv_bfloat16 g_Vtb[2*QKVPLN];        // [p][bh][s(16)][4KB]
__device__ float         g_S  [APLN];
__device__ __nv_bfloat16 g_A  [2*APLN];          // [p][bh][mt][s(16)][8KB]
__device__ float g_X [MTOT*DM];
__device__ float g_Y [MTOT*DM];
__device__ __nv_bfloat16 g_Yb[2u*4194304u];      // [p][mt][s(16)][8KB]
__device__ __nv_bfloat16 g_Hb[2u*1048576u];      // [p][mt][s(4)][8KB]
__device__ unsigned long long g_sacc[4];
__device__ unsigned char g_Wpk[5u*1024u*1024u];  // per W: [p][nt][s][8KB]

// ===================== asm helpers =====================
__device__ __forceinline__ uint32_t smem_to_u32(const void* p) {
    uint32_t a;
    asm("{ .reg .u64 t; cvta.to.shared.u64 t, %1; cvt.u32.u64 %0, t; }" : "=r"(a) : "l"(p));
    return a;
}
__device__ __forceinline__ void ldsm4(uint32_t* r, uint32_t addr) {
    asm volatile("ldmatrix.sync.aligned.m8n8.x4.shared.b16 {%0,%1,%2,%3}, [%4];"
        : "=r"(r[0]), "=r"(r[1]), "=r"(r[2]), "=r"(r[3]) : "r"(addr));
}
__device__ __forceinline__ void mma16816(float* c, const uint32_t* a, const uint32_t* b) {
    asm volatile("mma.sync.aligned.m16n8k16.row.col.f32.bf16.bf16.f32 "
        "{%0,%1,%2,%3}, {%4,%5,%6,%7}, {%8,%9}, {%0,%1,%2,%3};"
        : "+f"(c[0]), "+f"(c[1]), "+f"(c[2]), "+f"(c[3])
        : "r"(a[0]), "r"(a[1]), "r"(a[2]), "r"(a[3]), "r"(b[0]), "r"(b[1]));
}
__device__ __forceinline__ uint32_t pack_hi(float x, float y, float& lx, float& ly) {
    __nv_bfloat162 h = __floats2bfloat162_rn(x, y);
    lx = x - __bfloat162float(h.x);
    ly = y - __bfloat162float(h.y);
    return *reinterpret_cast<uint32_t*>(&h);
}
__device__ __forceinline__ uint32_t pack_lo(float lx, float ly) {
    __nv_bfloat162 l = __floats2bfloat162_rn(lx, ly);
    return *reinterpret_cast<uint32_t*>(&l);
}
// swizzled byte offset within an 8KB/4KB block of 64B rows; kb = byte in row [0,64)
__device__ __forceinline__ int swzoff(int r, int kb) {
    return r * 64 + ((((kb >> 4) ^ ((r >> 1) & 3)) << 4)) + (kb & 15);
}
#define BULK_G2S(dst, src, bytes, mbar) \
    asm volatile("cp.async.bulk.shared::cluster.global.mbarrier::complete_tx::bytes [%0], [%1], %2, [%3];" \
        :: "r"(dst), "l"(src), "r"(bytes), "r"(mbar) : "memory")
#define MBARRIER_INIT(mbar, cnt) \
    asm volatile("mbarrier.init.shared.b64 [%0], %1;" :: "r"((uint32_t)(mbar)), "r"((uint32_t)(cnt)) : "memory")
#define MBARRIER_EXPECT_TX(mbar, bytes) \
    asm volatile("mbarrier.arrive.expect_tx.shared.b64 _, [%0], %1;" :: "r"((uint32_t)(mbar)), "r"((uint32_t)(bytes)) : "memory")
#define MBARRIER_WAIT_PARITY(mbar, parity) do { \
    uint32_t _m = (uint32_t)(mbar); uint32_t _p = (uint32_t)(parity); uint32_t _d; \
    asm volatile("{\n\t.reg .pred p;\n\tmbarrier.try_wait.parity.acquire.cta.shared::cta.b64 p, [%1], %2;\n\tselp.b32 %0, 1, 0, p;\n\t}" \
        : "=r"(_d) : "r"(_m), "r"(_p) : "memory"); \
    if (!_d) { \
        asm volatile("{\n\t.reg .pred P1;\n\tWL_%=:\n\tmbarrier.try_wait.parity.acquire.cta.shared::cta.b64 P1, [%0], %1, 0x989680;\n\t@P1 bra.uni WD_%=;\n\tbra.uni WL_%=;\n\tWD_%=:\n\t}" \
            :: "r"(_m), "r"(_p) : "memory"); \
    } } while (0)

// ===================== weight pre-split (swizzled stage blocks) ====================
__global__ __launch_bounds__(256) void wconv_all(
    const float* __restrict__ Wq, const float* __restrict__ Wk,
    const float* __restrict__ Wv, const float* __restrict__ Wo,
    const float* __restrict__ Wi2, unsigned char* __restrict__ dst)
{
    if (blockIdx.x == 0 && threadIdx.x < 4) g_sacc[threadIdx.x] = 0ull;
    int bb = blockIdx.x;
    const float* W; unsigned char* d; int K;
    if      (bb < 512)  { W = Wq;  d = dst;              K = 512; }
    else if (bb < 1024) { W = Wk;  d = dst + 1048576u;   K = 512; bb -= 512; }
    else if (bb < 1536) { W = Wv;  d = dst + 2097152u;   K = 512; bb -= 1024; }
    else if (bb < 2048) { W = Wo;  d = dst + 3145728u;   K = 512; bb -= 1536; }
    else                { W = Wi2; d = dst + 4194304u;   K = 128; bb -= 2048; }
    int NK = (K == 512) ? 262144 : 65536;
    int S = K >> 5;
    int idx = bb * 256 + threadIdx.x;
    int halfK = K >> 1;
    int n = idx / halfK;
    int k = (idx - n * halfK) * 2;
    float x0 = W[(size_t)n * K + k];
    float x1 = W[(size_t)n * K + k + 1];
    float lx, ly;
    uint32_t hp = pack_hi(x0, x1, lx, ly);
    uint32_t lp = pack_lo(lx, ly);
    int nt = n >> 7, rr = n & 127, st = k >> 5, kb = (k & 31) * 2;
    size_t blk = ((size_t)nt * S + st) * 8192 + swzoff(rr, kb);
    *(uint32_t*)(d + blk)                  = hp;
    *(uint32_t*)(d + (size_t)NK * 2 + blk) = lp;
}

// ===================== input activation pre-split ==================================
__global__ __launch_bounds__(256) void aconv_kernel(
    const float* __restrict__ q, const float* __restrict__ k, const float* __restrict__ v)
{
    const float* src = blockIdx.y == 0 ? q : blockIdx.y == 1 ? k : v;
    char* dst = (char*)g_Ain + (size_t)blockIdx.y * 16777216u;
    size_t e = ((size_t)blockIdx.x * 256 + threadIdx.x) * 4;
    float4 x = *(const float4*)(src + e);
    float l0, l1, l2, l3;
    uint2 hp; hp.x = pack_hi(x.x, x.y, l0, l1); hp.y = pack_hi(x.z, x.w, l2, l3);
    uint2 lp; lp.x = pack_lo(l0, l1);           lp.y = pack_lo(l2, l3);
    int r = (int)(e >> 9), kk = (int)(e & 511);
    int mt = r >> 7, rr = r & 127, st = kk >> 5, kb = (kk & 31) * 2;   // kb mult of 8
    size_t blk = ((size_t)mt * 16 + st) * 8192 + swzoff(rr, kb);
    *(uint2*)(dst + blk)            = hp;
    *(uint2*)(dst + 8388608u + blk) = lp;
}

// ===================== unified pre-packed GEMM (bulk pipeline) =====================
// mode = mode0 + z. 0: plain fp32 C. 3: g_Y = g_X + scale*(acc+bias).
// 4: Q planes x1/8. 5: K planes. 6: V^T planes.
#define PGB 32768
#define PG_SMEM (2*PGB + 64)

__global__ __launch_bounds__(256, 2) void pgemm_kernel(
    const char* __restrict__ Ab0, long Apl, long Az,
    const char* __restrict__ Bb0, long Bpl, long Bz,
    int K, int mode0,
    const float* __restrict__ b0, const float* __restrict__ b1, const float* __restrict__ b2,
    float* __restrict__ C, const float* __restrict__ scale)
{
    extern __shared__ char sm[];
    const uint32_t sbase = smem_to_u32(sm);
    const uint32_t mb0 = sbase + 2 * PGB, mb1 = mb0 + 8;
    const int tid = threadIdx.x, wid = tid >> 5, lane = tid & 31;
    const int bx = blockIdx.x, by = blockIdx.y, z = blockIdx.z;
    const int mode = mode0 + z;
    const char* Ab = Ab0 + (size_t)z * Az;
    const char* Bb = Bb0 + (size_t)z * Bz;
    const float* bias = (z == 0) ? b0 : (z == 1) ? b1 : b2;
    const int S = K >> 5;
    const int bm = by * 128, bn = bx * 128;

    if (tid == 0) { MBARRIER_INIT(mb0, 1); MBARRIER_INIT(mb1, 1); }
    __syncthreads();

    float acc[16][4];
#pragma unroll
    for (int i = 0; i < 16; i++)
#pragma unroll
        for (int j = 0; j < 4; j++) acc[i][j] = 0.f;

    auto issue = [&](int s, int buf) {
        uint32_t mb = buf ? mb1 : mb0;
        uint32_t d = sbase + buf * PGB;
        MBARRIER_EXPECT_TX(mb, 32768);
        const char* As = Ab + (((size_t)by * S + s) << 13);
        const char* Bs = Bb + (((size_t)bx * S + s) << 13);
        BULK_G2S(d,         As,       8192, mb);
        BULK_G2S(d + 8192,  As + Apl, 8192, mb);
        BULK_G2S(d + 16384, Bs,       8192, mb);
        BULK_G2S(d + 24576, Bs + Bpl, 8192, mb);
    };

    const int wm = (wid >> 2) * 64, wn = (wid & 3) * 32;
    const int boff_n = ((lane >> 4) << 3) + (lane & 7);

    auto compute = [&](int buf) {
        uint32_t Ahi = sbase + buf * PGB;
        uint32_t Bhi = Ahi + 16384;
#pragma unroll
        for (int kh = 0; kh < 2; kh++) {
            const int qa = (kh * 2 + (lane >> 4)) << 4;
            const int qb = (kh * 2 + ((lane >> 3) & 1)) << 4;
            uint32_t bh[8], bl[8], a[16];
#pragma unroll
            for (int nf2 = 0; nf2 < 2; nf2++) {
                int rb = wn + nf2 * 16 + boff_n;
                uint32_t baddr = Bhi + swzoff(rb, qb);
                ldsm4(bh + nf2 * 4, baddr);
                ldsm4(bl + nf2 * 4, baddr + 8192);
            }
#pragma unroll
            for (int mf = 0; mf < 4; mf++) {
                int ra = wm + mf * 16 + (lane & 15);
                ldsm4(a + mf * 4, Ahi + swzoff(ra, qa));
            }
#pragma unroll
            for (int mf = 0; mf < 4; mf++)
#pragma unroll
                for (int nf = 0; nf < 4; nf++)
                    mma16816(acc[mf * 4 + nf], a + mf * 4, bh + nf * 2);
#pragma unroll
            for (int mf = 0; mf < 4; mf++)
#pragma unroll
                for (int nf = 0; nf < 4; nf++)
                    mma16816(acc[mf * 4 + nf], a + mf * 4, bl + nf * 2);
#pragma unroll
            for (int mf = 0; mf < 4; mf++) {
                int ra = wm + mf * 16 + (lane & 15);
                ldsm4(a + mf * 4, Ahi + 8192 + swzoff(ra, qa));
            }
#pragma unroll
            for (int mf = 0; mf < 4; mf++)
#pragma unroll
                for (int nf = 0; nf < 4; nf++)
                    mma16816(acc[mf * 4 + nf], a + mf * 4, bh + nf * 2);
        }
    };

    if (tid == 0) issue(0, 0);
    for (int s = 0; s < S; s++) {
        if (s + 1 < S && tid == 0) issue(s + 1, (s + 1) & 1);
        MBARRIER_WAIT_PARITY((s & 1) ? mb1 : mb0, (s >> 1) & 1);
        compute(s & 1);
        __syncthreads();
    }

    const float isc = (mode == 3) ? scale[0] : 0.f;
#pragma unroll
    for (int mf = 0; mf < 4; mf++) {
#pragma unroll
        for (int nf = 0; nf < 4; nf++) {
            float* cc = acc[mf * 4 + nf];
            int col = bn + wn + nf * 8 + (lane & 3) * 2;
            float bv0 = bias[col], bv1 = bias[col + 1];
#pragma unroll
            for (int rp = 0; rp < 2; rp++) {
                int m = bm + wm + mf * 16 + (lane >> 2) + rp * 8;
                float v0 = cc[rp * 2 + 0] + bv0;
                float v1 = cc[rp * 2 + 1] + bv1;
                if (mode == 0) {
                    *(float2*)(C + (size_t)m * DM + col) = make_float2(v0, v1);
                } else if (mode == 3) {
                    const float* ad = g_X + (size_t)m * DM + col;
                    *(float2*)(g_Y + (size_t)m * DM + col) =
                        make_float2(ad[0] + isc * v0, ad[1] + isc * v1);
                } else if (mode == 4 || mode == 5) {
                    if (mode == 4) { v0 *= 0.125f; v1 *= 0.125f; }
                    int bb = m >> 9, si = m & 511, hh = col >> 6, d = col & 63;
                    int bh_ = bb * 8 + hh, mt = si >> 7, rr = si & 127;
                    int st = d >> 5, kb = (d & 31) * 2;          // mult of 4
                    size_t blk = (((size_t)(bh_ * 4 + mt) * 2 + st) << 13) + swzoff(rr, kb);
                    char* base = (mode == 4) ? (char*)g_Qb : (char*)g_Kb;
                    float l0, l1;
                    uint32_t hp = pack_hi(v0, v1, l0, l1);
                    uint32_t lp = pack_lo(l0, l1);
                    *(uint32_t*)(base + blk)            = hp;
                    *(uint32_t*)(base + 8388608u + blk) = lp;
                } else {  // mode 6: V^T planes
                    int bb = m >> 9, si = m & 511, hh = col >> 6, d = col & 63;
                    int bh_ = bb * 8 + hh, st = si >> 5, kb = (si & 31) * 2;
                    size_t blk = ((size_t)(bh_ * 16 + st)) * 4096;
                    char* base = (char*)g_Vtb;
                    __nv_bfloat16 h0 = __float2bfloat16(v0);
                    __nv_bfloat16 h1 = __float2bfloat16(v1);
                    int o0 = swzoff(d, kb), o1 = swzoff(d + 1, kb);
                    *(__nv_bfloat16*)(base + blk + o0) = h0;
                    *(__nv_bfloat16*)(base + 8388608u + blk + o0) =
                        __float2bfloat16(v0 - __bfloat162float(h0));
                    *(__nv_bfloat16*)(base + blk + o1) = h1;
                    *(__nv_bfloat16*)(base + 8388608u + blk + o1) =
                        __float2bfloat16(v1 - __bfloat162float(h1));
                }
            }
        }
    }
}

// ===================== QK^T batched GEMM (bulk single-shot) ========================
#define SK_SMEM (65536 + 64)

__global__ __launch_bounds__(256, 2) void qk_kernel()
{
    if (blockIdx.x > blockIdx.y) return;
    extern __shared__ char sm[];
    const uint32_t sbase = smem_to_u32(sm);
    const uint32_t mb = sbase + 65536;
    const int bx = blockIdx.x, by = blockIdx.y;
    const int bn = bx * 128, bm = by * 128;
    const int bh = blockIdx.z;
    const int tid = threadIdx.x, wid = tid >> 5, lane = tid & 31;

    if (tid == 0) {
        MBARRIER_INIT(mb, 1);
        asm volatile("fence.proxy.async.shared::cta;" ::: "memory");
        MBARRIER_EXPECT_TX(mb, 65536);
        const char* Qb = (const char*)g_Qb;
        const char* Kb = (const char*)g_Kb;
#pragma unroll
        for (int p = 0; p < 2; p++)
#pragma unroll
            for (int s = 0; s < 2; s++) {
                const char* qsrc = Qb + (size_t)p * 8388608u + (((size_t)(bh * 4 + by) * 2 + s) << 13);
                const char* ksrc = Kb + (size_t)p * 8388608u + (((size_t)(bh * 4 + bx) * 2 + s) << 13);
                BULK_G2S(sbase + p * 16384 + s * 8192,         qsrc, 8192, mb);
                BULK_G2S(sbase + 32768 + p * 16384 + s * 8192, ksrc, 8192, mb);
            }
    }
    __syncthreads();
    MBARRIER_WAIT_PARITY(mb, 0);

    const int wm = (wid >> 2) * 64, wn = (wid & 3) * 32;
    const int boff_n = ((lane >> 4) << 3) + (lane & 7);

    float acc[16][4];
#pragma unroll
    for (int i = 0; i < 16; i++)
#pragma unroll
        for (int j = 0; j < 4; j++) acc[i][j] = 0.f;

#pragma unroll
    for (int kh = 0; kh < 4; kh++) {
        const int chunk = (kh >> 1) * 8192;
        const int qa = ((kh & 1) * 2 + (lane >> 4)) << 4;
        const int qb = ((kh & 1) * 2 + ((lane >> 3) & 1)) << 4;
        uint32_t bh_[8], bl_[8], a[16];
#pragma unroll
        for (int nf2 = 0; nf2 < 2; nf2++) {
            int rb = wn + nf2 * 16 + boff_n;
            uint32_t baddr = sbase + 32768 + chunk + swzoff(rb, qb);
            ldsm4(bh_ + nf2 * 4, baddr);
            ldsm4(bl_ + nf2 * 4, baddr + 16384);
        }
#pragma unroll
        for (int mf = 0; mf < 4; mf++) {
            int ra = wm + mf * 16 + (lane & 15);
            ldsm4(a + mf * 4, sbase + chunk + swzoff(ra, qa));
        }
#pragma unroll
        for (int mf = 0; mf < 4; mf++)
#pragma unroll
            for (int nf = 0; nf < 4; nf++)
                mma16816(acc[mf * 4 + nf], a + mf * 4, bh_ + nf * 2);
#pragma unroll
        for (int mf = 0; mf < 4; mf++)
#pragma unroll
            for (int nf = 0; nf < 4; nf++)
                mma16816(acc[mf * 4 + nf], a + mf * 4, bl_ + nf * 2);
#pragma unroll
        for (int mf = 0; mf < 4; mf++) {
            int ra = wm + mf * 16 + (lane & 15);
            ldsm4(a + mf * 4, sbase + 16384 + chunk + swzoff(ra, qa));
        }
#pragma unroll
        for (int mf = 0; mf < 4; mf++)
#pragma unroll
            for (int nf = 0; nf < 4; nf++)
                mma16816(acc[mf * 4 + nf], a + mf * 4, bh_ + nf * 2);
    }

    float* Sp = g_S + (size_t)bh * 512 * 512;
#pragma unroll
    for (int mf = 0; mf < 4; mf++)
#pragma unroll
        for (int nf = 0; nf < 4; nf++) {
            float* cc = acc[mf * 4 + nf];
            int col = bn + wn + nf * 8 + (lane & 3) * 2;
#pragma unroll
            for (int rp = 0; rp < 2; rp++) {
                int m = bm + wm + mf * 16 + (lane >> 2) + rp * 8;
                *(float2*)(Sp + (size_t)m * 512 + col) =
                    make_float2(cc[rp * 2], cc[rp * 2 + 1]);
            }
        }
}

// ===================== row kernel (softmax/scan/temporal -> A blocks) ==============
__global__ __launch_bounds__(256) void row_kernel(const float* __restrict__ gammas)
{
    const int bh = blockIdx.y, h = bh & 7;
    const int wid = threadIdx.x >> 5, lane = threadIdx.x & 31;
    const int i = blockIdx.x * 8 + wid;
    const int Ti = i >> 7;
    const int mt = i >> 7, rr = i & 127;
    char* Abase = (char*)g_A;

    if (i == 0) {
        uint2 zz = make_uint2(0u, 0u);
        int st = lane >> 3, kb = (lane & 7) * 8;
        size_t blk = ((size_t)(bh * 4 + 0) * 16 + st) * 8192 + swzoff(0, kb);
        *(uint2*)(Abase + blk)             = zz;
        *(uint2*)(Abase + 67108864u + blk) = zz;
        return;
    }

    float gv = gammas[h];
    float gam = -(fmaxf(gv, 0.f) + log1pf(__expf(-fabsf(gv))));

    const float4* Srow = (const float4*)(g_S + ((size_t)bh * 512 + i) * 512);
    float sc[4][4], e[4][4], ls[4];
#pragma unroll
    for (int t = 0; t < 4; t++) {
        if (t > Ti) { ls[t] = 0.f; continue; }
        float4 sv = Srow[lane + 32 * t];
        int j0 = 4 * (lane + 32 * t);
        sc[t][0] = (j0 + 0 < i) ? sv.x : NEG_INF;
        sc[t][1] = (j0 + 1 < i) ? sv.y : NEG_INF;
        sc[t][2] = (j0 + 2 < i) ? sv.z : NEG_INF;
        sc[t][3] = (j0 + 3 < i) ? sv.w : NEG_INF;
    }

    float m = NEG_INF;
#pragma unroll
    for (int t = 0; t < 4; t++) {
        if (t > Ti) break;
#pragma unroll
        for (int l = 0; l < 4; l++) m = fmaxf(m, sc[t][l]);
    }
#pragma unroll
    for (int off = 16; off; off >>= 1)
        m = fmaxf(m, __shfl_xor_sync(0xffffffffu, m, off));

#pragma unroll
    for (int t = 0; t < 4; t++) {
        if (t > Ti) break;
        ls[t] = 0.f;
#pragma unroll
        for (int l = 0; l < 4; l++) { e[t][l] = __expf(sc[t][l] - m); ls[t] += e[t][l]; }
    }
    float excl[4], tot[4];
#pragma unroll
    for (int t = 0; t < 4; t++) {
        if (t > Ti) break;
        float x = ls[t];
#pragma unroll
        for (int off = 1; off < 32; off <<= 1) {
            float y = __shfl_up_sync(0xffffffffu, x, off);
            if (lane >= off) x += y;
        }
        excl[t] = x - ls[t];
        tot[t]  = __shfl_sync(0xffffffffu, x, 31);
    }
    float baseA[4], T = 0.f;
#pragma unroll
    for (int t = 0; t < 4; t++) {
        if (t > Ti) break;
        baseA[t] = T; T += tot[t];
    }
    float invT = 1.f / T;

#pragma unroll
    for (int t = 0; t < 4; t++) {
        if (t > Ti) break;
        float run = baseA[t] + excl[t];
#pragma unroll
        for (int l = 0; l < 4; l++) {
            run += e[t][l];
            int j = 4 * lane + 128 * t + l;
            float suf  = fmaxf(T - run, 0.f);
            float dist = sqrtf(fmaxf(suf * invT * (float)(i - j), 0.f));
            float tmp  = __expf(dist * gam);
            tmp = fminf(fmaxf(tmp, 1e-5f), 1e5f);
            sc[t][l] = (j < i) ? sc[t][l] * tmp : NEG_INF;
        }
    }

    float m2 = NEG_INF;
#pragma unroll
    for (int t = 0; t < 4; t++) {
        if (t > Ti) break;
#pragma unroll
        for (int l = 0; l < 4; l++) m2 = fmaxf(m2, sc[t][l]);
    }
#pragma unroll
    for (int off = 16; off; off >>= 1)
        m2 = fmaxf(m2, __shfl_xor_sync(0xffffffffu, m2, off));
    float Z = 0.f;
#pragma unroll
    for (int t = 0; t < 4; t++) {
        if (t > Ti) break;
#pragma unroll
        for (int l = 0; l < 4; l++) { e[t][l] = __expf(sc[t][l] - m2); Z += e[t][l]; }
    }
#pragma unroll
    for (int off = 16; off; off >>= 1)
        Z += __shfl_xor_sync(0xffffffffu, Z, off);
    float invZ = 1.f / Z;

#pragma unroll
    for (int t = 0; t < 4; t++) {
        if (t > Ti) break;
        float a0 = e[t][0] * invZ, a1 = e[t][1] * invZ;
        float a2 = e[t][2] * invZ, a3 = e[t][3] * invZ;
        float l0, l1, l2, l3;
        uint2 hp; hp.x = pack_hi(a0, a1, l0, l1); hp.y = pack_hi(a2, a3, l2, l3);
        uint2 lp; lp.x = pack_lo(l0, l1);         lp.y = pack_lo(l2, l3);
        int st = (lane >> 3) + 4 * t, kb = (lane & 7) * 8;
        size_t blk = ((size_t)(bh * 4 + mt) * 16 + st) * 8192 + swzoff(rr, kb);
        *(uint2*)(Abase + blk)             = hp;
        *(uint2*)(Abase + 67108864u + blk) = lp;
    }
}

// ===================== AV batched GEMM (bulk pipeline, causal K-limit) =============
#define AVB 24576
#define AV_SMEM (2*AVB + 64)

__global__ __launch_bounds__(256, 2) void av_kernel()
{
    extern __shared__ char sm[];
    const uint32_t sbase = smem_to_u32(sm);
    const uint32_t mb0 = sbase + 2 * AVB, mb1 = mb0 + 8;
    const int mt = blockIdx.x;
    const int bm = mt * 128;
    const int bh = blockIdx.y;
    const int b = bh >> 3, h = bh & 7;
    const int tid = threadIdx.x, wid = tid >> 5, lane = tid & 31;
    const int nst = (bm + 128) >> 5;

    if (tid == 0) { MBARRIER_INIT(mb0, 1); MBARRIER_INIT(mb1, 1); }
    __syncthreads();

    float acc[8][4];
#pragma unroll
    for (int i = 0; i < 8; i++)
#pragma unroll
        for (int j = 0; j < 4; j++) acc[i][j] = 0.f;

    auto issue = [&](int s, int buf) {
        uint32_t mb = buf ? mb1 : mb0;
        uint32_t d = sbase + buf * AVB;
        MBARRIER_EXPECT_TX(mb, 24576);
        const char* Ap = (const char*)g_A + (((size_t)(bh * 4 + mt) * 16 + s) << 13);
        const char* Vp = (const char*)g_Vtb + ((size_t)(bh * 16 + s)) * 4096;
        BULK_G2S(d,         Ap,              8192, mb);
        BULK_G2S(d + 8192,  Ap + 67108864u,  8192, mb);
        BULK_G2S(d + 16384, Vp,              4096, mb);
        BULK_G2S(d + 20480, Vp + 8388608u,   4096, mb);
    };

    const int wm = (wid >> 1) * 32, wn = (wid & 1) * 32;
    const int boff_n = ((lane >> 4) << 3) + (lane & 7);

    auto compute = [&](int buf) {
        uint32_t Ab = sbase + buf * AVB;
        uint32_t Vb = Ab + 16384;
#pragma unroll
        for (int kh = 0; kh < 2; kh++) {
            const int qa = (kh * 2 + (lane >> 4)) << 4;
            const int qb = (kh * 2 + ((lane >> 3) & 1)) << 4;
            uint32_t bh_[8], bl_[8], a[8];
#pragma unroll
            for (int nf2 = 0; nf2 < 2; nf2++) {
                int rb = wn + nf2 * 16 + boff_n;
                uint32_t baddr = Vb + swzoff(rb, qb);
                ldsm4(bh_ + nf2 * 4, baddr);
                ldsm4(bl_ + nf2 * 4, baddr + 4096);
            }
#pragma unroll
            for (int mf = 0; mf < 2; mf++) {
                int ra = wm + mf * 16 + (lane & 15);
                ldsm4(a + mf * 4, Ab + swzoff(ra, qa));
            }
#pragma unroll
            for (int mf = 0; mf < 2; mf++)
#pragma unroll
                for (int nf = 0; nf < 4; nf++)
                    mma16816(acc[mf * 4 + nf], a + mf * 4, bh_ + nf * 2);
#pragma unroll
            for (int mf = 0; mf < 2; mf++)
#pragma unroll
                for (int nf = 0; nf < 4; nf++)
                    mma16816(acc[mf * 4 + nf], a + mf * 4, bl_ + nf * 2);
#pragma unroll
            for (int mf = 0; mf < 2; mf++) {
                int ra = wm + mf * 16 + (lane & 15);
                ldsm4(a + mf * 4, Ab + 8192 + swzoff(ra, qa));
            }
#pragma unroll
            for (int mf = 0; mf < 2; mf++)
#pragma unroll
                for (int nf = 0; nf < 4; nf++)
                    mma16816(acc[mf * 4 + nf], a + mf * 4, bh_ + nf * 2);
        }
    };

    if (tid == 0) issue(0, 0);
    for (int s = 0; s < nst; s++) {
        if (s + 1 < nst && tid == 0) issue(s + 1, (s + 1) & 1);
        MBARRIER_WAIT_PARITY((s & 1) ? mb1 : mb0, (s >> 1) & 1);
        compute(s & 1);
        __syncthreads();
    }

#pragma unroll
    for (int mf = 0; mf < 2; mf++)
#pragma unroll
        for (int nf = 0; nf < 4; nf++) {
            float* cc = acc[mf * 4 + nf];
            int col = wn + nf * 8 + (lane & 3) * 2;
#pragma unroll
            for (int rp = 0; rp < 2; rp++) {
                int mrow = bm + wm + mf * 16 + (lane >> 2) + rp * 8;
                *(float2*)(g_X + ((size_t)(b * 512 + mrow)) * 512 + h * 64 + col) =
                    make_float2(cc[rp * 2], cc[rp * 2 + 1]);
            }
        }
}

// ===================== parallel norm01 stats =====================
__global__ __launch_bounds__(256) void stats_kernel(
    const int* __restrict__ sgap, const int* __restrict__ pcount)
{
    __shared__ long long sh[32];
    int idx = blockIdx.x * 256 + threadIdx.x;
    long long a = sgap[idx], b = pcount[idx];
    long long s0 = a, q0 = a * a, s1 = b, q1 = b * b;
#pragma unroll
    for (int off = 16; off; off >>= 1) {
        s0 += __shfl_xor_sync(0xffffffffu, s0, off);
        q0 += __shfl_xor_sync(0xffffffffu, q0, off);
        s1 += __shfl_xor_sync(0xffffffffu, s1, off);
        q1 += __shfl_xor_sync(0xffffffffu, q1, off);
    }
    int wd = threadIdx.x >> 5, ln = threadIdx.x & 31;
    if (ln == 0) { sh[wd] = s0; sh[8+wd] = q0; sh[16+wd] = s1; sh[24+wd] = q1; }
    __syncthreads();
    if (threadIdx.x == 0) {
        long long S0=0,Q0=0,S1=0,Q1=0;
        for (int i = 0; i < 8; i++) { S0+=sh[i]; Q0+=sh[8+i]; S1+=sh[16+i]; Q1+=sh[24+i]; }
        atomicAdd(&g_sacc[0], (unsigned long long)S0);
        atomicAdd(&g_sacc[1], (unsigned long long)Q0);
        atomicAdd(&g_sacc[2], (unsigned long long)S1);
        atomicAdd(&g_sacc[3], (unsigned long long)Q1);
    }
}

// ===================== interference hidden layer -> bf16 blocks ===================
__global__ __launch_bounds__(256) void hidden_kernel(
    const int* __restrict__ sgap, const int* __restrict__ pcount,
    const float* __restrict__ Wi1, const float* __restrict__ bi1)
{
    float n = (float)MTOT;
    float S0 = (float)(long long)g_sacc[0], Q0 = (float)(long long)g_sacc[1];
    float S1 = (float)(long long)g_sacc[2], Q1 = (float)(long long)g_sacc[3];
    float m0 = S0 / n, m1 = S1 / n;
    float v0 = (Q0 - n*m0*m0) / (n - 1.f);
    float v1 = (Q1 - n*m1*m1) / (n - 1.f);
    float inv0 = 1.f / (sqrtf(fmaxf(v0, 0.f)) + 1e-6f);
    float inv1 = 1.f / (sqrtf(fmaxf(v1, 0.f)) + 1e-6f);

    int idx = blockIdx.x * 256 + threadIdx.x;   // over 8192*64
    int r = idx >> 6, c2 = (idx & 63) * 2;
    float ii0 = 0.5f * (tanhf(((float)sgap[r]   - m0) * inv0) + 1.f);
    float ii1 = 0.5f * (tanhf(((float)pcount[r] - m1) * inv1) + 1.f);
    float h0 = fmaxf(ii0 * Wi1[2*c2+0] + ii1 * Wi1[2*c2+1] + bi1[c2],   0.f);
    float h1 = fmaxf(ii0 * Wi1[2*c2+2] + ii1 * Wi1[2*c2+3] + bi1[c2+1], 0.f);
    float l0, l1;
    uint32_t hp = pack_hi(h0, h1, l0, l1);
    uint32_t lp = pack_lo(l0, l1);
    int mt = r >> 7, rr = r & 127, st = c2 >> 5, kb = (c2 & 31) * 2;
    size_t blk = ((size_t)mt * 4 + st) * 8192 + swzoff(rr, kb);
    char* base = (char*)g_Hb;
    *(uint32_t*)(base + blk)            = hp;
    *(uint32_t*)(base + 2097152u + blk) = lp;
}

// ===================== LayerNorm + pack to bf16 blocks ============================
__global__ __launch_bounds__(256) void ln_pack_kernel(
    const float* __restrict__ gw, const float* __restrict__ bw)
{
    int r = blockIdx.x * 8 + (threadIdx.x >> 5);
    int lane = threadIdx.x & 31;
    const float4* row = (const float4*)(g_Y + (size_t)r * DM);
    float4 xv[4];
    float s = 0.f, q = 0.f;
#pragma unroll
    for (int c = 0; c < 4; c++) {
        xv[c] = row[lane + 32 * c];
        s += xv[c].x + xv[c].y + xv[c].z + xv[c].w;
        q += xv[c].x*xv[c].x + xv[c].y*xv[c].y + xv[c].z*xv[c].z + xv[c].w*xv[c].w;
    }
#pragma unroll
    for (int off = 16; off; off >>= 1) {
        s += __shfl_xor_sync(0xffffffffu, s, off);
        q += __shfl_xor_sync(0xffffffffu, q, off);
    }
    float mu   = s * (1.f / 512.f);
    float rstd = rsqrtf(q * (1.f / 512.f) - mu * mu + 1e-5f);
    int mt = r >> 7, rr = r & 127;
    char* base = (char*)g_Yb;
#pragma unroll
    for (int c = 0; c < 4; c++) {
        float4 g4 = ((const float4*)gw)[lane + 32 * c];
        float4 b4 = ((const float4*)bw)[lane + 32 * c];
        float n0 = (xv[c].x - mu) * rstd * g4.x + b4.x;
        float n1 = (xv[c].y - mu) * rstd * g4.y + b4.y;
        float n2 = (xv[c].z - mu) * rstd * g4.z + b4.z;
        float n3 = (xv[c].w - mu) * rstd * g4.w + b4.w;
        float l0, l1, l2, l3;
        uint2 hp; hp.x = pack_hi(n0, n1, l0, l1); hp.y = pack_hi(n2, n3, l2, l3);
        uint2 lp; lp.x = pack_lo(l0, l1);         lp.y = pack_lo(l2, l3);
        int st = (lane >> 3) + 4 * c, kb = (lane & 7) * 8;
        size_t blk = ((size_t)mt * 16 + st) * 8192 + swzoff(rr, kb);
        *(uint2*)(base + blk)            = hp;
        *(uint2*)(base + 8388608u + blk) = lp;
    }
}

// ===================== launcher =====================
extern "C" void kernel_launch(void* const* d_in, const int* in_sizes, int n_in,
                              void* d_out, int out_size)
{
    const float* q      = (const float*)d_in[0];
    const float* k      = (const float*)d_in[1];
    const float* v      = (const float*)d_in[2];
    const int*   sgap   = (const int*)d_in[3];
    const int*   pcount = (const int*)d_in[4];
    const float* Wq = (const float*)d_in[5];  const float* bq = (const float*)d_in[6];
    const float* Wk = (const float*)d_in[7];  const float* bk = (const float*)d_in[8];
    const float* Wv = (const float*)d_in[9];  const float* bv = (const float*)d_in[10];
    const float* Wo = (const float*)d_in[11]; const float* bo = (const float*)d_in[12];
    const float* gammas = (const float*)d_in[13];
    const float* ln_g = (const float*)d_in[14]; const float* ln_b = (const float*)d_in[15];
    const float* Wi1 = (const float*)d_in[16];  const float* bi1 = (const float*)d_in[17];
    const float* Wi2 = (const float*)d_in[18];  const float* bi2 = (const float*)d_in[19];
    const float* iscale = (const float*)d_in[20];
    float* out = (float*)d_out;

    char *Ain, *Yb, *Hb;
    unsigned char* Wpk;
    cudaGetSymbolAddress((void**)&Ain, g_Ain);
    cudaGetSymbolAddress((void**)&Yb,  g_Yb);
    cudaGetSymbolAddress((void**)&Hb,  g_Hb);
    cudaGetSymbolAddress((void**)&Wpk, g_Wpk);

    cudaFuncSetAttribute(pgemm_kernel, cudaFuncAttributeMaxDynamicSharedMemorySize, PG_SMEM);
    cudaFuncSetAttribute(qk_kernel, cudaFuncAttributeMaxDynamicSharedMemorySize, SK_SMEM);
    cudaFuncSetAttribute(av_kernel, cudaFuncAttributeMaxDynamicSharedMemorySize, AV_SMEM);

    wconv_all<<<2176, 256>>>(Wq, Wk, Wv, Wo, Wi2, Wpk);
    aconv_kernel<<<dim3(4096, 3), 256>>>(q, k, v);
    stats_kernel<<<32, 256>>>(sgap, pcount);

    // fused QKV projections
    pgemm_kernel<<<dim3(4, 64, 3), 256, PG_SMEM>>>(
        Ain, 8388608L, 16777216L, (const char*)Wpk, 524288L, 1048576L,
        512, 4, bq, bk, bv, nullptr, nullptr);

    qk_kernel<<<dim3(4, 4, 128), 256, SK_SMEM>>>();
    row_kernel<<<dim3(64, 128), 256>>>(gammas);
    av_kernel<<<dim3(4, 128), 256, AV_SMEM>>>();

    hidden_kernel<<<2048, 256>>>(sgap, pcount, Wi1, bi1);
    // Y = X + iscale*(H @ Wi2^T + bi2)
    pgemm_kernel<<<dim3(4, 64, 1), 256, PG_SMEM>>>(
        Hb, 2097152L, 0L, (const char*)Wpk + 4194304u, 131072L, 0L,
        128, 3, bi2, nullptr, nullptr, nullptr, iscale);

    ln_pack_kernel<<<1024, 256>>>(ln_g, ln_b);

    // out = LN(Y) @ Wo^T + bo
    pgemm_kernel<<<dim3(4, 64, 1), 256, PG_SMEM>>>(
        Yb, 8388608L, 0L, (const char*)Wpk + 3145728u, 524288L, 0L,
        512, 0, bo, nullptr, nullptr, out, nullptr);
}